// round 7
// baseline (speedup 1.0000x reference)
#include <cuda_runtime.h>
#include <cuda_bf16.h>
#include <cstdint>

#define TT 2048
#define BB 16
#define DD 1024
#define NN 64
#define MT (TT * BB)      // 32768 rows
#define NC 256            // k|v|q|a packed columns
#define PAD_T 8           // zero padding time-steps (device globals zero-init)
#define CCH 16            // chunk size for pass B
#define NCH (TT / CCH)    // 128 chunks

// ------------------------- device scratch (no allocs allowed) ---------------
__device__ float g_proj[(size_t)(MT + PAD_T * BB) * NC];     // 33 MB + pad
__device__ float g_gram[(size_t)(MT + PAD_T * BB) * 4];      // kk1..kk4 per row
__device__ float2 g_ac[(size_t)MT * NN];                     // (alpha, cc) 16 MB
__device__ float g_u[(size_t)NCH * BB * NN * CCH];           // 8 MB suffix weights
__device__ float g_Ptot[(size_t)NCH * BB * NN];              // chunk alpha-products
__device__ float g_Scs[(size_t)NCH * BB * NN * NN];          // chunk-start states 32 MB
__device__ __nv_bfloat16 g_xhi[(size_t)MT * DD];
__device__ __nv_bfloat16 g_xlo[(size_t)MT * DD];
__device__ __nv_bfloat16 g_whi[(size_t)NC * DD];
__device__ __nv_bfloat16 g_wlo[(size_t)NC * DD];

// ---------------------------------------------------------------------------
// Convert X -> bf16 hi/lo split.
// ---------------------------------------------------------------------------
__global__ __launch_bounds__(256) void convert_x(const float* __restrict__ x) {
    size_t t = (size_t)blockIdx.x * blockDim.x + threadIdx.x;
    size_t base = t * 16;
#pragma unroll
    for (int l = 0; l < 4; l++) {
        float4 v = *(const float4*)(x + base + l * 4);
        __nv_bfloat16 h0 = __float2bfloat16(v.x);
        __nv_bfloat16 h1 = __float2bfloat16(v.y);
        __nv_bfloat16 h2 = __float2bfloat16(v.z);
        __nv_bfloat16 h3 = __float2bfloat16(v.w);
        __nv_bfloat16 l0 = __float2bfloat16(v.x - __bfloat162float(h0));
        __nv_bfloat16 l1 = __float2bfloat16(v.y - __bfloat162float(h1));
        __nv_bfloat16 l2 = __float2bfloat16(v.z - __bfloat162float(h2));
        __nv_bfloat16 l3 = __float2bfloat16(v.w - __bfloat162float(h3));
        __nv_bfloat162 hp0 = __halves2bfloat162(h0, h1);
        __nv_bfloat162 hp1 = __halves2bfloat162(h2, h3);
        __nv_bfloat162 lp0 = __halves2bfloat162(l0, l1);
        __nv_bfloat162 lp1 = __halves2bfloat162(l2, l3);
        *(uint2*)&g_xhi[base + l * 4] = make_uint2(*(uint32_t*)&hp0, *(uint32_t*)&hp1);
        *(uint2*)&g_xlo[base + l * 4] = make_uint2(*(uint32_t*)&lp0, *(uint32_t*)&lp1);
    }
}

__global__ __launch_bounds__(256) void convert_w(
    const float* __restrict__ Wk, const float* __restrict__ Wv,
    const float* __restrict__ Wq, const float* __restrict__ Wa)
{
    int e4 = blockIdx.x * 256 + threadIdx.x;
    int base = e4 * 4;
    int row = base >> 10;
    int colk = base & 1023;
    int cb = row >> 6, n = row & 63;
    const float* W = (cb == 0) ? Wk : (cb == 1) ? Wv : (cb == 2) ? Wq : Wa;
    float4 v = *(const float4*)(W + (size_t)n * DD + colk);
    __nv_bfloat16 h0 = __float2bfloat16(v.x);
    __nv_bfloat16 h1 = __float2bfloat16(v.y);
    __nv_bfloat16 h2 = __float2bfloat16(v.z);
    __nv_bfloat16 h3 = __float2bfloat16(v.w);
    __nv_bfloat16 l0 = __float2bfloat16(v.x - __bfloat162float(h0));
    __nv_bfloat16 l1 = __float2bfloat16(v.y - __bfloat162float(h1));
    __nv_bfloat16 l2 = __float2bfloat16(v.z - __bfloat162float(h2));
    __nv_bfloat16 l3 = __float2bfloat16(v.w - __bfloat162float(h3));
    __nv_bfloat162 hp0 = __halves2bfloat162(h0, h1);
    __nv_bfloat162 hp1 = __halves2bfloat162(h2, h3);
    __nv_bfloat162 lp0 = __halves2bfloat162(l0, l1);
    __nv_bfloat162 lp1 = __halves2bfloat162(l2, l3);
    *(uint2*)&g_whi[(size_t)row * DD + colk] = make_uint2(*(uint32_t*)&hp0, *(uint32_t*)&hp1);
    *(uint2*)&g_wlo[(size_t)row * DD + colk] = make_uint2(*(uint32_t*)&lp0, *(uint32_t*)&lp1);
}

// ---------------------------------------------------------------------------
// Tensor-core GEMM (unchanged): g_proj = X @ Wcat^T, 3x bf16 split.
// ---------------------------------------------------------------------------
#define GBM 128
#define GBN 128
#define GBK 32
#define SA  40

#define MMA16816(d, a, b0v, b1v)                                              \
    asm volatile("mma.sync.aligned.m16n8k16.row.col.f32.bf16.bf16.f32 "       \
                 "{%0,%1,%2,%3}, {%4,%5,%6,%7}, {%8,%9}, {%0,%1,%2,%3};"      \
                 : "+f"(d[0]), "+f"(d[1]), "+f"(d[2]), "+f"(d[3])             \
                 : "r"(a[0]), "r"(a[1]), "r"(a[2]), "r"(a[3]),                \
                   "r"(b0v), "r"(b1v));

__global__ __launch_bounds__(256) void mma_gemm() {
    __shared__ alignas(16) __nv_bfloat16 Ah[GBM * SA];
    __shared__ alignas(16) __nv_bfloat16 Al[GBM * SA];
    __shared__ alignas(16) __nv_bfloat16 Bh[GBN * SA];
    __shared__ alignas(16) __nv_bfloat16 Bl[GBN * SA];

    const int tid = threadIdx.x;
    const int wid = tid >> 5, lane = tid & 31;
    const int wm = wid & 3, wn = wid >> 2;
    const int row0 = blockIdx.x * GBM;
    const int col0 = blockIdx.y * GBN;
    const int g = lane >> 2, tg = lane & 3;

    float acc[2][8][4];
#pragma unroll
    for (int a = 0; a < 2; a++)
#pragma unroll
        for (int b = 0; b < 8; b++)
#pragma unroll
            for (int r = 0; r < 4; r++) acc[a][b][r] = 0.f;

    for (int kb = 0; kb < DD; kb += GBK) {
#pragma unroll
        for (int l = 0; l < 2; l++) {
            int f = tid + 256 * l;
            int r = f >> 2, kc = f & 3;
            size_t ga = (size_t)(row0 + r) * DD + kb + kc * 8;
            size_t gb = (size_t)(col0 + r) * DD + kb + kc * 8;
            *(uint4*)&Ah[r * SA + kc * 8] = *(const uint4*)&g_xhi[ga];
            *(uint4*)&Al[r * SA + kc * 8] = *(const uint4*)&g_xlo[ga];
            *(uint4*)&Bh[r * SA + kc * 8] = *(const uint4*)&g_whi[gb];
            *(uint4*)&Bl[r * SA + kc * 8] = *(const uint4*)&g_wlo[gb];
        }
        __syncthreads();

#pragma unroll
        for (int ks = 0; ks < GBK; ks += 16) {
            uint32_t afh[2][4], afl[2][4];
            const int kk2 = ks + 2 * tg;
#pragma unroll
            for (int ms = 0; ms < 2; ms++) {
                int rr = wm * 32 + ms * 16 + g;
                afh[ms][0] = *(const uint32_t*)&Ah[rr * SA + kk2];
                afh[ms][1] = *(const uint32_t*)&Ah[(rr + 8) * SA + kk2];
                afh[ms][2] = *(const uint32_t*)&Ah[rr * SA + kk2 + 8];
                afh[ms][3] = *(const uint32_t*)&Ah[(rr + 8) * SA + kk2 + 8];
                afl[ms][0] = *(const uint32_t*)&Al[rr * SA + kk2];
                afl[ms][1] = *(const uint32_t*)&Al[(rr + 8) * SA + kk2];
                afl[ms][2] = *(const uint32_t*)&Al[rr * SA + kk2 + 8];
                afl[ms][3] = *(const uint32_t*)&Al[(rr + 8) * SA + kk2 + 8];
            }
#pragma unroll
            for (int ns = 0; ns < 8; ns++) {
                int nr = wn * 64 + ns * 8 + g;
                uint32_t bh0 = *(const uint32_t*)&Bh[nr * SA + kk2];
                uint32_t bh1 = *(const uint32_t*)&Bh[nr * SA + kk2 + 8];
                uint32_t bl0 = *(const uint32_t*)&Bl[nr * SA + kk2];
                uint32_t bl1 = *(const uint32_t*)&Bl[nr * SA + kk2 + 8];
#pragma unroll
                for (int ms = 0; ms < 2; ms++) {
                    MMA16816(acc[ms][ns], afh[ms], bh0, bh1);
                    MMA16816(acc[ms][ns], afh[ms], bl0, bl1);
                    MMA16816(acc[ms][ns], afl[ms], bh0, bh1);
                }
            }
        }
        __syncthreads();
    }

#pragma unroll
    for (int ms = 0; ms < 2; ms++)
#pragma unroll
        for (int ns = 0; ns < 8; ns++) {
            int m = row0 + wm * 32 + ms * 16 + g;
            int n = col0 + wn * 64 + ns * 8 + tg * 2;
            *(float2*)&g_proj[(size_t)m * NC + n] =
                make_float2(acc[ms][ns][0], acc[ms][ns][1]);
            *(float2*)&g_proj[(size_t)(m + 8) * NC + n] =
                make_float2(acc[ms][ns][2], acc[ms][ns][3]);
        }
}

// ---------------------------------------------------------------------------
// Gram kernel: row r = t*16+b -> [kk1,kk2,kk3,kk4], kkd = k_t . k_{t+d}.
// Reads beyond MT hit zero padding. One warp per row.
// ---------------------------------------------------------------------------
__global__ __launch_bounds__(256) void gram_kernel() {
    const int wid = threadIdx.x >> 5, lane = threadIdx.x & 31;
    const int row = blockIdx.x * 8 + wid;
    const float* P0 = g_proj + (size_t)row * NC;

    float k0a = P0[lane], k0b = P0[32 + lane];
    float d[4];
#pragma unroll
    for (int dd = 0; dd < 4; dd++) {
        const float* Pd = g_proj + (size_t)(row + (dd + 1) * BB) * NC;
        d[dd] = k0a * Pd[lane] + k0b * Pd[32 + lane];
    }
#pragma unroll
    for (int m = 1; m < 32; m <<= 1)
#pragma unroll
        for (int e = 0; e < 4; e++)
            d[e] += __shfl_xor_sync(0xFFFFFFFFu, d[e], m);

    if (lane == 0)
        *(float4*)&g_gram[(size_t)row * 4] = make_float4(d[0], d[1], d[2], d[3]);
}

// ---------------------------------------------------------------------------
// Pass A: gates-only sequential scan (produces alpha, cc per (t,b,i)).
// Same E-ladder as R5 minus q/F/output machinery. 128 blocks x 128 thr
// (8 rows/block, 16 lanes/row) -> 1 warp/SMSP on 128 SMs, MIO ~9 ops/step.
// ---------------------------------------------------------------------------
__device__ __forceinline__ float fast_tanh(float x) {
    float r;
    asm("tanh.approx.f32 %0, %1;" : "=f"(r) : "f"(x));
    return r;
}

__global__ __launch_bounds__(128) void scanA_kernel(
    const float* __restrict__ S_in,
    const float* __restrict__ dA,
    const float* __restrict__ bA)
{
    const int b  = blockIdx.x >> 3;
    const int rg = blockIdx.x & 7;
    const int il = threadIdx.x >> 4;     // local row 0..7
    const int i  = rg * 8 + il;          // global row 0..63
    const int c  = threadIdx.x & 15;
    const int j0 = c << 2;

    float S[4];
    {
        const float* sp = S_in + ((size_t)b * NN + i) * NN + j0;
#pragma unroll
        for (int r = 0; r < 4; r++) S[r] = sp[r];
    }
    const float da = dA[i];
    const float ba_ = bA[i];

    const float* Pk = g_proj + (size_t)b * NC + j0;
    const float* Pv = g_proj + (size_t)b * NC + 64 + i;
    const float* Pa = g_proj + (size_t)b * NC + 192 + i;
    const float* Pg = g_gram + (size_t)b * 4;
    const size_t STEPP = (size_t)BB * NC;
    const size_t STEPG = (size_t)BB * 4;
    float2* Pac = g_ac + (size_t)b * NN + i;
    const size_t STEPA = (size_t)BB * NN;

    float kr[8][4], gr[4][4], vr[4], ar[4];

    auto ldk = [&](int t, int slot) {
        float4 f = *(const float4*)(Pk + (size_t)t * STEPP);
        kr[slot][0] = f.x; kr[slot][1] = f.y; kr[slot][2] = f.z; kr[slot][3] = f.w;
    };
    auto ldg_ = [&](int t, int slot) {
        float4 g = *(const float4*)(Pg + (size_t)t * STEPG);
        gr[slot][0] = g.x; gr[slot][1] = g.y; gr[slot][2] = g.z; gr[slot][3] = g.w;
    };
    auto ldva = [&](int t, int slot) {
        vr[slot] = Pv[(size_t)t * STEPP];
        ar[slot] = Pa[(size_t)t * STEPP] + ba_;
    };

#pragma unroll
    for (int s = 0; s < 8; s++) ldk(s, s);
#pragma unroll
    for (int s = 0; s < 4; s++) { ldg_(s, s); ldva(s, s); }

    // prologue: r = S.k0, E1..E4 = S.k_{1..4}
    float r, E1, E2, E3, E4;
    {
        float p[5] = {0, 0, 0, 0, 0};
#pragma unroll
        for (int j = 0; j < 4; j++) {
            p[0] = fmaf(S[j], kr[0][j], p[0]);
            p[1] = fmaf(S[j], kr[1][j], p[1]);
            p[2] = fmaf(S[j], kr[2][j], p[2]);
            p[3] = fmaf(S[j], kr[3][j], p[3]);
            p[4] = fmaf(S[j], kr[4][j], p[4]);
        }
#pragma unroll
        for (int m = 1; m < 16; m <<= 1)
#pragma unroll
            for (int e = 0; e < 5; e++)
                p[e] += __shfl_xor_sync(0xFFFFFFFFu, p[e], m);
        r = p[0]; E1 = p[1]; E2 = p[2]; E3 = p[3]; E4 = p[4];
    }

    for (int t0 = 0; t0 < TT; t0 += 8) {
#pragma unroll
        for (int p = 0; p < 8; p++) {
            const int t = t0 + p;
            const float* kc  = kr[p];
            const float* kt5 = kr[(p + 5) & 7];
            const float* g   = gr[p & 3];
            const float vt = vr[p & 3];
            const float at = ar[p & 3];

            // ---- critical chain ----
            float xg = fmaf(da, r, at);
            float al = fmaf(0.5f, fast_tanh(0.5f * xg), 0.5f);
            float cc = (1.0f - al) * vt;
            float rn = fmaf(al, E1, cc * g[0]);

            // ---- S update + deep tree (S_t . k_{t+5}) ----
            float e4 = 0.f;
#pragma unroll
            for (int j = 0; j < 4; j++) {
                S[j] = fmaf(al, S[j], cc * kc[j]);
                e4 = fmaf(S[j], kt5[j], e4);
            }

            // ---- scalar hops ----
            float E1n = fmaf(al, E2, cc * g[1]);
            float E2n = fmaf(al, E3, cc * g[2]);
            float E3n = fmaf(al, E4, cc * g[3]);

            e4 += __shfl_xor_sync(0xFFFFFFFFu, e4, 1);
            e4 += __shfl_xor_sync(0xFFFFFFFFu, e4, 2);
            e4 += __shfl_xor_sync(0xFFFFFFFFu, e4, 4);
            e4 += __shfl_xor_sync(0xFFFFFFFFu, e4, 8);

            if (c == 0) Pac[(size_t)t * STEPA] = make_float2(al, cc);

            r = rn; E1 = E1n; E2 = E2n; E3 = E3n; E4 = e4;

            ldk(t + 8, p);
            ldg_(t + 4, p & 3);
            ldva(t + 4, p & 3);
        }
    }
}

// ---------------------------------------------------------------------------
// B0: per (chunk,b,i): suffix weights u_s = cc_s * prod_{u>s} alpha_u, and
// P = prod of all 16 alphas. All weights are products of alphas (<=1): stable.
// ---------------------------------------------------------------------------
__global__ __launch_bounds__(256) void b0_suffix() {
    int idx = blockIdx.x * 256 + threadIdx.x;    // 0..131071
    int i  = idx & 63;
    int b  = (idx >> 6) & 15;
    int ch = idx >> 10;

    float al[CCH], cc[CCH];
#pragma unroll
    for (int s = 0; s < CCH; s++) {
        float2 v = g_ac[((size_t)(ch * CCH + s) * BB + b) * NN + i];
        al[s] = v.x; cc[s] = v.y;
    }
    float u[CCH];
    float suf = 1.f;
#pragma unroll
    for (int s = CCH - 1; s >= 0; s--) {
        u[s] = cc[s] * suf;
        suf *= al[s];
    }
    float* U = g_u + ((size_t)ch * BB * NN + (size_t)b * NN + i) * CCH;
#pragma unroll
    for (int s = 0; s < CCH; s += 4)
        *(float4*)(U + s) = make_float4(u[s], u[s + 1], u[s + 2], u[s + 3]);
    g_Ptot[(size_t)ch * BB * NN + (size_t)b * NN + i] = suf;
}

// ---------------------------------------------------------------------------
// B1: chunk-state scan. Thread owns S[b,i,j]; 128 sequential chunk hops.
// Writes state BEFORE each chunk to g_Scs; final state -> out tail.
// ---------------------------------------------------------------------------
__global__ __launch_bounds__(256) void b1_states(
    const float* __restrict__ S_in, float* __restrict__ out)
{
    int idx = blockIdx.x * 256 + threadIdx.x;    // 0..65535
    int j = idx & 63;
    int i = (idx >> 6) & 63;
    int b = idx >> 12;

    float S = S_in[((size_t)b * NN + i) * NN + j];
    const size_t ui_base = ((size_t)b * NN + i) * CCH;
    const size_t sc_base = ((size_t)b * NN + i) * NN + j;

    for (int ch = 0; ch < NCH; ch++) {
        g_Scs[(size_t)ch * BB * NN * NN + sc_base] = S;
        const float* U = g_u + (size_t)ch * BB * NN * CCH + ui_base;
        float u[CCH];
#pragma unroll
        for (int s = 0; s < CCH; s += 4) {
            float4 f = *(const float4*)(U + s);
            u[s] = f.x; u[s + 1] = f.y; u[s + 2] = f.z; u[s + 3] = f.w;
        }
        float acc = 0.f;
#pragma unroll
        for (int s = 0; s < CCH; s++)
            acc = fmaf(u[s], g_proj[((size_t)(ch * CCH + s) * BB + b) * NC + j], acc);
        float P = g_Ptot[(size_t)ch * BB * NN + (size_t)b * NN + i];
        S = fmaf(P, S, acc);
    }
    out[(size_t)TT * BB * NN + ((size_t)b * NN + i) * NN + j] = S;
}

// ---------------------------------------------------------------------------
// B3: outputs. Block per (b,chunk), 64 threads (thread = row i).
// smem: K,Q tiles + D = K.Q^T. Then per row: g_t = Scs_row . q_t and the
// triangular DP  o_t = pi_t*g_t + sum_{s<=t} cc_s*W(s,t)*D[s,t].
// ---------------------------------------------------------------------------
__global__ __launch_bounds__(64) void b3_out(float* __restrict__ out) {
    const int b  = blockIdx.x & 15;
    const int ch = blockIdx.x >> 4;
    const int tid = threadIdx.x;          // = i

    __shared__ float Ks[CCH][68];
    __shared__ float Qs[CCH][68];
    __shared__ float Dm[CCH][CCH];

    // load K/Q tiles: thread tid loads column j=tid for all 16 steps
#pragma unroll
    for (int s = 0; s < CCH; s++) {
        const float* P = g_proj + ((size_t)(ch * CCH + s) * BB + b) * NC;
        Ks[s][tid] = P[tid];
        Qs[s][tid] = P[128 + tid];
    }
    __syncthreads();

    // D[s][t] = k_s . q_t  (4 entries per thread)
#pragma unroll
    for (int e = 0; e < 4; e++) {
        int id = tid * 4 + e;
        int s = id >> 4, t = id & 15;
        float a = 0.f;
#pragma unroll
        for (int j = 0; j < NN; j++) a = fmaf(Ks[s][j], Qs[t][j], a);
        Dm[s][t] = a;
    }
    __syncthreads();

    // Scs row for i = tid
    float Sr[NN];
    {
        const float* P = g_Scs + (size_t)ch * BB * NN * NN + ((size_t)b * NN + tid) * NN;
#pragma unroll
        for (int j = 0; j < NN; j += 4) {
            float4 f = *(const float4*)(P + j);
            Sr[j] = f.x; Sr[j + 1] = f.y; Sr[j + 2] = f.z; Sr[j + 3] = f.w;
        }
    }

    // g_t = Scs_row . q_t
    float gt[CCH];
#pragma unroll
    for (int t = 0; t < CCH; t++) {
        float a = 0.f;
#pragma unroll
        for (int j = 0; j < NN; j++) a = fmaf(Sr[j], Qs[t][j], a);
        gt[t] = a;
    }

    // alpha/cc for this row
    float al[CCH], cc[CCH];
#pragma unroll
    for (int s = 0; s < CCH; s++) {
        float2 v = g_ac[((size_t)(ch * CCH + s) * BB + b) * NN + tid];
        al[s] = v.x; cc[s] = v.y;
    }

    // triangular DP
    float w[CCH];
    float pi = 1.f;
#pragma unroll
    for (int t = 0; t < CCH; t++) {
        float a = al[t];
        pi *= a;
#pragma unroll
        for (int s = 0; s < CCH; s++)
            if (s < t) w[s] *= a;
        w[t] = cc[t];
        float o = pi * gt[t];
#pragma unroll
        for (int s = 0; s < CCH; s++)
            if (s <= t) o = fmaf(w[s], Dm[s][t], o);
        float sg = fmaf(0.5f, fast_tanh(0.5f * o), 0.5f);
        out[((size_t)(ch * CCH + t) * BB + b) * NN + tid] = o * o * sg;
    }
}

extern "C" void kernel_launch(void* const* d_in, const int* in_sizes, int n_in,
                              void* d_out, int out_size) {
    const float* x  = (const float*)d_in[0];
    const float* S  = (const float*)d_in[1];
    const float* Wk = (const float*)d_in[2];
    const float* Wv = (const float*)d_in[3];
    const float* Wq = (const float*)d_in[4];
    const float* Wa = (const float*)d_in[5];
    const float* da = (const float*)d_in[6];
    const float* ba = (const float*)d_in[7];
    float* out = (float*)d_out;

    convert_x<<<MT * DD / (256 * 16), 256>>>(x);
    convert_w<<<NC * DD / (256 * 4), 256>>>(Wk, Wv, Wq, Wa);
    dim3 ggrid(MT / GBM, NC / GBN);
    mma_gemm<<<ggrid, 256>>>();
    gram_kernel<<<MT / 8, 256>>>();
    scanA_kernel<<<BB * 8, 128>>>(S, da, ba);
    b0_suffix<<<NCH * BB * NN / 256, 256>>>();
    b1_states<<<BB * NN * NN / 256, 256>>>(S, out);
    b3_out<<<NCH * BB, 64>>>(out);
}

// round 9
// speedup vs baseline: 1.4139x; 1.4139x over previous
#include <cuda_runtime.h>
#include <cuda_bf16.h>
#include <cstdint>

#define TT 2048
#define BB 16
#define DD 1024
#define NN 64
#define MT (TT * BB)      // 32768 rows
#define NC 256            // k|v|q|a packed columns
#define PAD_T 16          // zero padding time-steps (device globals zero-init)
#define CCH 16            // chunk size
#define NCH (TT / CCH)    // 128 chunks

// ------------------------- device scratch (no allocs allowed) ---------------
__device__ float g_proj[(size_t)(MT + PAD_T * BB) * NC];       // 33 MB + pad
__device__ float g_gramc[(size_t)(NCH + 1) * BB * 256];        // in-chunk k-Gram (+pad)
__device__ float2 g_ac[(size_t)MT * NN];                       // (alpha, cc)
__device__ float g_Scs[(size_t)NCH * BB * NN * NN];            // chunk-start states
__device__ __nv_bfloat16 g_xhi[(size_t)MT * DD];
__device__ __nv_bfloat16 g_xlo[(size_t)MT * DD];
__device__ __nv_bfloat16 g_whi[(size_t)NC * DD];
__device__ __nv_bfloat16 g_wlo[(size_t)NC * DD];

// ---------------------------------------------------------------------------
// Convert X -> bf16 hi/lo split.
// ---------------------------------------------------------------------------
__global__ __launch_bounds__(256) void convert_x(const float* __restrict__ x) {
    size_t t = (size_t)blockIdx.x * blockDim.x + threadIdx.x;
    size_t base = t * 16;
#pragma unroll
    for (int l = 0; l < 4; l++) {
        float4 v = *(const float4*)(x + base + l * 4);
        __nv_bfloat16 h0 = __float2bfloat16(v.x);
        __nv_bfloat16 h1 = __float2bfloat16(v.y);
        __nv_bfloat16 h2 = __float2bfloat16(v.z);
        __nv_bfloat16 h3 = __float2bfloat16(v.w);
        __nv_bfloat16 l0 = __float2bfloat16(v.x - __bfloat162float(h0));
        __nv_bfloat16 l1 = __float2bfloat16(v.y - __bfloat162float(h1));
        __nv_bfloat16 l2 = __float2bfloat16(v.z - __bfloat162float(h2));
        __nv_bfloat16 l3 = __float2bfloat16(v.w - __bfloat162float(h3));
        __nv_bfloat162 hp0 = __halves2bfloat162(h0, h1);
        __nv_bfloat162 hp1 = __halves2bfloat162(h2, h3);
        __nv_bfloat162 lp0 = __halves2bfloat162(l0, l1);
        __nv_bfloat162 lp1 = __halves2bfloat162(l2, l3);
        *(uint2*)&g_xhi[base + l * 4] = make_uint2(*(uint32_t*)&hp0, *(uint32_t*)&hp1);
        *(uint2*)&g_xlo[base + l * 4] = make_uint2(*(uint32_t*)&lp0, *(uint32_t*)&lp1);
    }
}

__global__ __launch_bounds__(256) void convert_w(
    const float* __restrict__ Wk, const float* __restrict__ Wv,
    const float* __restrict__ Wq, const float* __restrict__ Wa)
{
    int e4 = blockIdx.x * 256 + threadIdx.x;
    int base = e4 * 4;
    int row = base >> 10;
    int colk = base & 1023;
    int cb = row >> 6, n = row & 63;
    const float* W = (cb == 0) ? Wk : (cb == 1) ? Wv : (cb == 2) ? Wq : Wa;
    float4 v = *(const float4*)(W + (size_t)n * DD + colk);
    __nv_bfloat16 h0 = __float2bfloat16(v.x);
    __nv_bfloat16 h1 = __float2bfloat16(v.y);
    __nv_bfloat16 h2 = __float2bfloat16(v.z);
    __nv_bfloat16 h3 = __float2bfloat16(v.w);
    __nv_bfloat16 l0 = __float2bfloat16(v.x - __bfloat162float(h0));
    __nv_bfloat16 l1 = __float2bfloat16(v.y - __bfloat162float(h1));
    __nv_bfloat16 l2 = __float2bfloat16(v.z - __bfloat162float(h2));
    __nv_bfloat16 l3 = __float2bfloat16(v.w - __bfloat162float(h3));
    __nv_bfloat162 hp0 = __halves2bfloat162(h0, h1);
    __nv_bfloat162 hp1 = __halves2bfloat162(h2, h3);
    __nv_bfloat162 lp0 = __halves2bfloat162(l0, l1);
    __nv_bfloat162 lp1 = __halves2bfloat162(l2, l3);
    *(uint2*)&g_whi[(size_t)row * DD + colk] = make_uint2(*(uint32_t*)&hp0, *(uint32_t*)&hp1);
    *(uint2*)&g_wlo[(size_t)row * DD + colk] = make_uint2(*(uint32_t*)&lp0, *(uint32_t*)&lp1);
}

// ---------------------------------------------------------------------------
// Tensor-core GEMM (unchanged): g_proj = X @ Wcat^T, 3x bf16 split.
// ---------------------------------------------------------------------------
#define GBM 128
#define GBN 128
#define GBK 32
#define SA  40

#define MMA16816(d, a, b0v, b1v)                                              \
    asm volatile("mma.sync.aligned.m16n8k16.row.col.f32.bf16.bf16.f32 "       \
                 "{%0,%1,%2,%3}, {%4,%5,%6,%7}, {%8,%9}, {%0,%1,%2,%3};"      \
                 : "+f"(d[0]), "+f"(d[1]), "+f"(d[2]), "+f"(d[3])             \
                 : "r"(a[0]), "r"(a[1]), "r"(a[2]), "r"(a[3]),                \
                   "r"(b0v), "r"(b1v));

__global__ __launch_bounds__(256) void mma_gemm() {
    __shared__ alignas(16) __nv_bfloat16 Ah[GBM * SA];
    __shared__ alignas(16) __nv_bfloat16 Al[GBM * SA];
    __shared__ alignas(16) __nv_bfloat16 Bh[GBN * SA];
    __shared__ alignas(16) __nv_bfloat16 Bl[GBN * SA];

    const int tid = threadIdx.x;
    const int wid = tid >> 5, lane = tid & 31;
    const int wm = wid & 3, wn = wid >> 2;
    const int row0 = blockIdx.x * GBM;
    const int col0 = blockIdx.y * GBN;
    const int g = lane >> 2, tg = lane & 3;

    float acc[2][8][4];
#pragma unroll
    for (int a = 0; a < 2; a++)
#pragma unroll
        for (int b = 0; b < 8; b++)
#pragma unroll
            for (int r = 0; r < 4; r++) acc[a][b][r] = 0.f;

    for (int kb = 0; kb < DD; kb += GBK) {
#pragma unroll
        for (int l = 0; l < 2; l++) {
            int f = tid + 256 * l;
            int r = f >> 2, kc = f & 3;
            size_t ga = (size_t)(row0 + r) * DD + kb + kc * 8;
            size_t gb = (size_t)(col0 + r) * DD + kb + kc * 8;
            *(uint4*)&Ah[r * SA + kc * 8] = *(const uint4*)&g_xhi[ga];
            *(uint4*)&Al[r * SA + kc * 8] = *(const uint4*)&g_xlo[ga];
            *(uint4*)&Bh[r * SA + kc * 8] = *(const uint4*)&g_whi[gb];
            *(uint4*)&Bl[r * SA + kc * 8] = *(const uint4*)&g_wlo[gb];
        }
        __syncthreads();

#pragma unroll
        for (int ks = 0; ks < GBK; ks += 16) {
            uint32_t afh[2][4], afl[2][4];
            const int kk2 = ks + 2 * tg;
#pragma unroll
            for (int ms = 0; ms < 2; ms++) {
                int rr = wm * 32 + ms * 16 + g;
                afh[ms][0] = *(const uint32_t*)&Ah[rr * SA + kk2];
                afh[ms][1] = *(const uint32_t*)&Ah[(rr + 8) * SA + kk2];
                afh[ms][2] = *(const uint32_t*)&Ah[rr * SA + kk2 + 8];
                afh[ms][3] = *(const uint32_t*)&Ah[(rr + 8) * SA + kk2 + 8];
                afl[ms][0] = *(const uint32_t*)&Al[rr * SA + kk2];
                afl[ms][1] = *(const uint32_t*)&Al[(rr + 8) * SA + kk2];
                afl[ms][2] = *(const uint32_t*)&Al[rr * SA + kk2 + 8];
                afl[ms][3] = *(const uint32_t*)&Al[(rr + 8) * SA + kk2 + 8];
            }
#pragma unroll
            for (int ns = 0; ns < 8; ns++) {
                int nr = wn * 64 + ns * 8 + g;
                uint32_t bh0 = *(const uint32_t*)&Bh[nr * SA + kk2];
                uint32_t bh1 = *(const uint32_t*)&Bh[nr * SA + kk2 + 8];
                uint32_t bl0 = *(const uint32_t*)&Bl[nr * SA + kk2];
                uint32_t bl1 = *(const uint32_t*)&Bl[nr * SA + kk2 + 8];
#pragma unroll
                for (int ms = 0; ms < 2; ms++) {
                    MMA16816(acc[ms][ns], afh[ms], bh0, bh1);
                    MMA16816(acc[ms][ns], afh[ms], bl0, bl1);
                    MMA16816(acc[ms][ns], afl[ms], bh0, bh1);
                }
            }
        }
        __syncthreads();
    }

#pragma unroll
    for (int ms = 0; ms < 2; ms++)
#pragma unroll
        for (int ns = 0; ns < 8; ns++) {
            int m = row0 + wm * 32 + ms * 16 + g;
            int n = col0 + wn * 64 + ns * 8 + tg * 2;
            *(float2*)&g_proj[(size_t)m * NC + n] =
                make_float2(acc[ms][ns][0], acc[ms][ns][1]);
            *(float2*)&g_proj[(size_t)(m + 8) * NC + n] =
                make_float2(acc[ms][ns][2], acc[ms][ns][3]);
        }
}

// ---------------------------------------------------------------------------
// In-chunk Gram: for (chunk,b): G[t*16+u] = k_u . k_t (64-dim dots).
// Block per (chunk,b), 256 threads, K tile staged in smem.
// ---------------------------------------------------------------------------
__global__ __launch_bounds__(256) void gramc_kernel() {
    const int b  = blockIdx.x & 15;
    const int ch = blockIdx.x >> 4;
    const int tid = threadIdx.x;
    __shared__ float Ks[16][68];

    {
        const int s = tid >> 4, j4 = (tid & 15) * 4;
        float4 kv = *(const float4*)(g_proj + ((size_t)(ch * CCH + s) * BB + b) * NC + j4);
        *(float4*)&Ks[s][j4] = kv;
    }
    __syncthreads();

    const int t = tid >> 4, u = tid & 15;
    float acc = 0.f;
#pragma unroll
    for (int j = 0; j < 64; j++) acc = fmaf(Ks[t][j], Ks[u][j], acc);
    g_gramc[((size_t)ch * BB + b) * 256 + t * 16 + u] = acc;
}

// ---------------------------------------------------------------------------
// scanA: chunked sequential gate pass. 64 blocks (b, quarter) x 256 threads
// = 16 rows x 16 lanes. Per chunk:
//   ph2 (scalar threads, one per row): 16 steps of PURE register math —
//        r_t = pi*g[t] + sum_{u<t} ws[u]*G[u][t]; gate; update ws/pi.
//   ph3 (all lanes): S = pi*S + sum_s ws[s]*k_s (rank-16);  write Scs;
//        batched g-dots for next chunk (16 independent shfl trees).
// Tiles (K, Gram, v, a) double-buffered in smem, LDGs issued a phase ahead.
// ---------------------------------------------------------------------------
__device__ __forceinline__ float fast_tanh(float x) {
    float r;
    asm("tanh.approx.f32 %0, %1;" : "=f"(r) : "f"(x));
    return r;
}

__global__ __launch_bounds__(256) void scanA_kernel(
    const float* __restrict__ S_in,
    const float* __restrict__ dA,
    const float* __restrict__ bA,
    float* __restrict__ out)
{
    const int b  = blockIdx.x >> 2;
    const int qr = blockIdx.x & 3;
    const int i0 = qr * 16;
    const int tid = threadIdx.x;
    const int il = tid >> 4;          // row in block 0..15
    const int i  = i0 + il;           // global row
    const int c  = tid & 15;          // lane in row
    const int j0 = c * 4;

    __shared__ float Kbuf[2][16 * 68];
    __shared__ float Gbuf[2][256];
    __shared__ float Vbuf[2][16][16];   // [buf][s][row]
    __shared__ float Abuf[2][16][16];
    __shared__ float Wsbuf[16][20];

    // staging roles (happen to match (il, c)):
    const int sk = il, jk = j0;               // K: float4 per thread
    const int sv = il, iv = c;                // v/a: scalar per thread

    float S0, S1, S2, S3;
    {
        float4 si = *(const float4*)(S_in + ((size_t)b * NN + i) * NN + j0);
        S0 = si.x; S1 = si.y; S2 = si.z; S3 = si.w;
        *(float4*)(g_Scs + ((size_t)b * NN + i) * NN + j0) = si;   // Scs[0]
    }
    float da_ = 0.f, ba_ = 0.f;
    if (c == 0) { da_ = dA[i]; ba_ = bA[i]; }

    // ---- prologue: stage chunk 0 tiles ----
    {
        float4 kpre = *(const float4*)(g_proj + ((size_t)sk * BB + b) * NC + jk);
        float4 gpre = make_float4(0, 0, 0, 0);
        if (tid < 64) gpre = *(const float4*)(g_gramc + (size_t)b * 256 + tid * 4);
        float vpre = g_proj[((size_t)sv * BB + b) * NC + 64 + i0 + iv];
        float apre = g_proj[((size_t)sv * BB + b) * NC + 192 + i0 + iv];
        *(float4*)&Kbuf[0][sk * 68 + jk] = kpre;
        if (tid < 64) *(float4*)&Gbuf[0][tid * 4] = gpre;
        Vbuf[0][sv][iv] = vpre;
        Abuf[0][sv][iv] = apre;
    }
    __syncthreads();

    // ---- prologue g-dots: g[d] = S_init . k_d (chunk 0) ----
    float gre[16];
    {
        float pd[16];
#pragma unroll
        for (int d = 0; d < 16; d++) {
            float4 k4 = *(const float4*)&Kbuf[0][d * 68 + j0];
            pd[d] = S0 * k4.x + S1 * k4.y + S2 * k4.z + S3 * k4.w;
        }
#pragma unroll
        for (int m = 1; m < 16; m <<= 1)
#pragma unroll
            for (int d = 0; d < 16; d++)
                pd[d] += __shfl_xor_sync(0xFFFFFFFFu, pd[d], m);
#pragma unroll
        for (int d = 0; d < 16; d++) gre[d] = pd[d];
    }

    for (int ch = 0; ch < NCH; ch++) {
        const int cb = ch & 1, nb = cb ^ 1;

        // ---- issue LDGs for chunk ch+1 (consumed next phases; pad-safe) ----
        const size_t tb1 = (size_t)((ch + 1) * CCH) * BB + b;
        float4 kpre = *(const float4*)(g_proj + (tb1 + (size_t)sk * BB) * NC + jk);
        float4 gpre = make_float4(0, 0, 0, 0);
        if (tid < 64)
            gpre = *(const float4*)(g_gramc + ((size_t)(ch + 1) * BB + b) * 256 + tid * 4);
        float vpre = g_proj[(tb1 + (size_t)sv * BB) * NC + 64 + i0 + iv];
        float apre = g_proj[(tb1 + (size_t)sv * BB) * NC + 192 + i0 + iv];

        // ---- ph2: scalar recursion (one thread per row) ----
        if (c == 0) {
            float ws[16];
            float pi = 1.f;
            float2* acp = g_ac + ((size_t)(ch * CCH) * BB + b) * NN + i;
#pragma unroll
            for (int s = 0; s < 16; s++) {
                float kc[16];
#pragma unroll
                for (int u4 = 0; u4 < 16; u4 += 4) {
                    float4 f = *(const float4*)&Gbuf[cb][s * 16 + u4];
                    kc[u4] = f.x; kc[u4 + 1] = f.y; kc[u4 + 2] = f.z; kc[u4 + 3] = f.w;
                }
                float a0 = 0.f, a1 = 0.f, a2 = 0.f, a3 = 0.f;
#pragma unroll
                for (int u = 0; u < 16; u++) {
                    if (u < s) {
                        float tmp = ws[u] * kc[u];
                        if ((u & 3) == 0) a0 += tmp;
                        else if ((u & 3) == 1) a1 += tmp;
                        else if ((u & 3) == 2) a2 += tmp;
                        else a3 += tmp;
                    }
                }
                float r = fmaf(pi, gre[s], (a0 + a1) + (a2 + a3));
                float xg = fmaf(da_, r, Abuf[cb][s][il] + ba_);
                float al = fmaf(0.5f, fast_tanh(0.5f * xg), 0.5f);
                float cv = (1.0f - al) * Vbuf[cb][s][il];
                acp[(size_t)s * BB * NN] = make_float2(al, cv);
                pi *= al;
#pragma unroll
                for (int u = 0; u < 16; u++)
                    if (u < s) ws[u] *= al;
                ws[s] = cv;
            }
#pragma unroll
            for (int u = 0; u < 16; u++) Wsbuf[il][u] = ws[u];
            Wsbuf[il][16] = pi;
        }
        __syncthreads();   // ws visible; ph2 consumers of old tiles done

        // ---- ph3a: stage prefetched tiles into buffer nb ----
        *(float4*)&Kbuf[nb][sk * 68 + jk] = kpre;
        if (tid < 64) *(float4*)&Gbuf[nb][tid * 4] = gpre;
        Vbuf[nb][sv][iv] = vpre;
        Abuf[nb][sv][iv] = apre;

        // ---- ph3b: S rank-16 update from Kbuf[cb] + Wsbuf ----
        {
            float pi2 = Wsbuf[il][16];
            float n0 = pi2 * S0, n1 = pi2 * S1, n2 = pi2 * S2, n3 = pi2 * S3;
#pragma unroll
            for (int s = 0; s < 16; s++) {
                float w = Wsbuf[il][s];
                float4 k4 = *(const float4*)&Kbuf[cb][s * 68 + j0];
                n0 = fmaf(w, k4.x, n0);
                n1 = fmaf(w, k4.y, n1);
                n2 = fmaf(w, k4.z, n2);
                n3 = fmaf(w, k4.w, n3);
            }
            S0 = n0; S1 = n1; S2 = n2; S3 = n3;
            float4 sv4 = make_float4(S0, S1, S2, S3);
            if (ch < NCH - 1)
                *(float4*)(g_Scs + (size_t)(ch + 1) * BB * NN * NN
                           + ((size_t)b * NN + i) * NN + j0) = sv4;
            else
                *(float4*)(out + (size_t)TT * BB * NN
                           + ((size_t)b * NN + i) * NN + j0) = sv4;
        }
        __syncthreads();   // Kbuf[nb] visible

        // ---- ph3c: g-dots for chunk ch+1 (16 batched trees) ----
        {
            float pd[16];
#pragma unroll
            for (int d = 0; d < 16; d++) {
                float4 k4 = *(const float4*)&Kbuf[nb][d * 68 + j0];
                pd[d] = S0 * k4.x + S1 * k4.y + S2 * k4.z + S3 * k4.w;
            }
#pragma unroll
            for (int m = 1; m < 16; m <<= 1)
#pragma unroll
                for (int d = 0; d < 16; d++)
                    pd[d] += __shfl_xor_sync(0xFFFFFFFFu, pd[d], m);
#pragma unroll
            for (int d = 0; d < 16; d++) gre[d] = pd[d];
        }
    }
}

// ---------------------------------------------------------------------------
// b3: outputs. Block per (b,chunk), 64 threads (thread = row i).
// ---------------------------------------------------------------------------
__global__ __launch_bounds__(64) void b3_out(float* __restrict__ out) {
    const int b  = blockIdx.x & 15;
    const int ch = blockIdx.x >> 4;
    const int tid = threadIdx.x;          // = i

    __shared__ float Ks[CCH][68];
    __shared__ float Qs[CCH][68];
    __shared__ float Dm[CCH][CCH];

#pragma unroll
    for (int s = 0; s < CCH; s++) {
        const float* P = g_proj + ((size_t)(ch * CCH + s) * BB + b) * NC;
        Ks[s][tid] = P[tid];
        Qs[s][tid] = P[128 + tid];
    }
    __syncthreads();

#pragma unroll
    for (int e = 0; e < 4; e++) {
        int id = tid * 4 + e;
        int s = id >> 4, t = id & 15;
        float a = 0.f;
#pragma unroll
        for (int j = 0; j < NN; j++) a = fmaf(Ks[s][j], Qs[t][j], a);
        Dm[s][t] = a;
    }
    __syncthreads();

    float Sr[NN];
    {
        const float* P = g_Scs + (size_t)ch * BB * NN * NN + ((size_t)b * NN + tid) * NN;
#pragma unroll
        for (int j = 0; j < NN; j += 4) {
            float4 f = *(const float4*)(P + j);
            Sr[j] = f.x; Sr[j + 1] = f.y; Sr[j + 2] = f.z; Sr[j + 3] = f.w;
        }
    }

    float gt[CCH];
#pragma unroll
    for (int t = 0; t < CCH; t++) {
        float a = 0.f;
#pragma unroll
        for (int j = 0; j < NN; j++) a = fmaf(Sr[j], Qs[t][j], a);
        gt[t] = a;
    }

    float al[CCH], cc[CCH];
#pragma unroll
    for (int s = 0; s < CCH; s++) {
        float2 v = g_ac[((size_t)(ch * CCH + s) * BB + b) * NN + tid];
        al[s] = v.x; cc[s] = v.y;
    }

    float w[CCH];
    float pi = 1.f;
#pragma unroll
    for (int t = 0; t < CCH; t++) {
        float a = al[t];
        pi *= a;
#pragma unroll
        for (int s = 0; s < CCH; s++)
            if (s < t) w[s] *= a;
        w[t] = cc[t];
        float o = pi * gt[t];
#pragma unroll
        for (int s = 0; s < CCH; s++)
            if (s <= t) o = fmaf(w[s], Dm[s][t], o);
        float sg = fmaf(0.5f, fast_tanh(0.5f * o), 0.5f);
        out[((size_t)(ch * CCH + t) * BB + b) * NN + tid] = o * o * sg;
    }
}

extern "C" void kernel_launch(void* const* d_in, const int* in_sizes, int n_in,
                              void* d_out, int out_size) {
    const float* x  = (const float*)d_in[0];
    const float* S  = (const float*)d_in[1];
    const float* Wk = (const float*)d_in[2];
    const float* Wv = (const float*)d_in[3];
    const float* Wq = (const float*)d_in[4];
    const float* Wa = (const float*)d_in[5];
    const float* da = (const float*)d_in[6];
    const float* ba = (const float*)d_in[7];
    float* out = (float*)d_out;

    convert_x<<<MT * DD / (256 * 16), 256>>>(x);
    convert_w<<<NC * DD / (256 * 4), 256>>>(Wk, Wv, Wq, Wa);
    dim3 ggrid(MT / GBM, NC / GBN);
    mma_gemm<<<ggrid, 256>>>();
    gramc_kernel<<<NCH * BB, 256>>>();
    scanA_kernel<<<BB * 4, 256>>>(S, da, ba, out);
    b3_out<<<NCH * BB, 64>>>(out);
}

// round 10
// speedup vs baseline: 1.6483x; 1.1658x over previous
#include <cuda_runtime.h>
#include <cuda_bf16.h>
#include <cstdint>

#define TT 2048
#define BB 16
#define DD 1024
#define NN 64
#define MT (TT * BB)      // 32768 rows
#define NC 256            // k|v|q|a packed columns
#define PAD_T 16          // zero padding time-steps (device globals zero-init)
#define CCH 16            // chunk size
#define NCH (TT / CCH)    // 128 chunks

// ------------------------- device scratch (no allocs allowed) ---------------
__device__ float g_proj[(size_t)(MT + PAD_T * BB) * NC];       // 33 MB + pad
__device__ float g_gramc[(size_t)(NCH + 1) * BB * 256];        // in-chunk k-Gram (+pad)
__device__ float2 g_ac[(size_t)MT * NN];                       // (alpha, cc)
__device__ float g_Scs[(size_t)NCH * BB * NN * NN];            // chunk-start states
__device__ __nv_bfloat16 g_whi[(size_t)NC * DD];
__device__ __nv_bfloat16 g_wlo[(size_t)NC * DD];

// ---------------------------------------------------------------------------
// Convert W (4 matrices stacked: k|v|q|a) -> bf16 hi/lo
// ---------------------------------------------------------------------------
__global__ __launch_bounds__(256) void convert_w(
    const float* __restrict__ Wk, const float* __restrict__ Wv,
    const float* __restrict__ Wq, const float* __restrict__ Wa)
{
    int e4 = blockIdx.x * 256 + threadIdx.x;
    int base = e4 * 4;
    int row = base >> 10;
    int colk = base & 1023;
    int cb = row >> 6, n = row & 63;
    const float* W = (cb == 0) ? Wk : (cb == 1) ? Wv : (cb == 2) ? Wq : Wa;
    float4 v = *(const float4*)(W + (size_t)n * DD + colk);
    __nv_bfloat16 h0 = __float2bfloat16(v.x);
    __nv_bfloat16 h1 = __float2bfloat16(v.y);
    __nv_bfloat16 h2 = __float2bfloat16(v.z);
    __nv_bfloat16 h3 = __float2bfloat16(v.w);
    __nv_bfloat16 l0 = __float2bfloat16(v.x - __bfloat162float(h0));
    __nv_bfloat16 l1 = __float2bfloat16(v.y - __bfloat162float(h1));
    __nv_bfloat16 l2 = __float2bfloat16(v.z - __bfloat162float(h2));
    __nv_bfloat16 l3 = __float2bfloat16(v.w - __bfloat162float(h3));
    __nv_bfloat162 hp0 = __halves2bfloat162(h0, h1);
    __nv_bfloat162 hp1 = __halves2bfloat162(h2, h3);
    __nv_bfloat162 lp0 = __halves2bfloat162(l0, l1);
    __nv_bfloat162 lp1 = __halves2bfloat162(l2, l3);
    *(uint2*)&g_whi[(size_t)row * DD + colk] = make_uint2(*(uint32_t*)&hp0, *(uint32_t*)&hp1);
    *(uint2*)&g_wlo[(size_t)row * DD + colk] = make_uint2(*(uint32_t*)&lp0, *(uint32_t*)&lp1);
}

// ---------------------------------------------------------------------------
// Fused tensor-core GEMM: g_proj = X(f32) @ Wcat^T, 3x bf16 split (hh+hl+lh).
// X is loaded as f32 and converted to hi/lo in-kernel (no convert_x pass).
// Register double-buffer: next iter's LDGs issued before the MMA phase.
// Grid: (col-blocks fastest) so both N-blocks of a row-block share X via L2.
// ---------------------------------------------------------------------------
#define GBM 128
#define GBN 128
#define GBK 32
#define SA  40

#define MMA16816(d, a, b0v, b1v)                                              \
    asm volatile("mma.sync.aligned.m16n8k16.row.col.f32.bf16.bf16.f32 "       \
                 "{%0,%1,%2,%3}, {%4,%5,%6,%7}, {%8,%9}, {%0,%1,%2,%3};"      \
                 : "+f"(d[0]), "+f"(d[1]), "+f"(d[2]), "+f"(d[3])             \
                 : "r"(a[0]), "r"(a[1]), "r"(a[2]), "r"(a[3]),                \
                   "r"(b0v), "r"(b1v));

__device__ __forceinline__ void split4(float4 v, uint32_t& h01, uint32_t& h23,
                                       uint32_t& l01, uint32_t& l23) {
    __nv_bfloat16 h0 = __float2bfloat16(v.x);
    __nv_bfloat16 h1 = __float2bfloat16(v.y);
    __nv_bfloat16 h2 = __float2bfloat16(v.z);
    __nv_bfloat16 h3 = __float2bfloat16(v.w);
    __nv_bfloat16 l0 = __float2bfloat16(v.x - __bfloat162float(h0));
    __nv_bfloat16 l1 = __float2bfloat16(v.y - __bfloat162float(h1));
    __nv_bfloat16 l2 = __float2bfloat16(v.z - __bfloat162float(h2));
    __nv_bfloat16 l3 = __float2bfloat16(v.w - __bfloat162float(h3));
    __nv_bfloat162 hp0 = __halves2bfloat162(h0, h1);
    __nv_bfloat162 hp1 = __halves2bfloat162(h2, h3);
    __nv_bfloat162 lp0 = __halves2bfloat162(l0, l1);
    __nv_bfloat162 lp1 = __halves2bfloat162(l2, l3);
    h01 = *(uint32_t*)&hp0; h23 = *(uint32_t*)&hp1;
    l01 = *(uint32_t*)&lp0; l23 = *(uint32_t*)&lp1;
}

__global__ __launch_bounds__(256) void mma_gemm(const float* __restrict__ x) {
    __shared__ alignas(16) __nv_bfloat16 Ah[GBM * SA];
    __shared__ alignas(16) __nv_bfloat16 Al[GBM * SA];
    __shared__ alignas(16) __nv_bfloat16 Bh[GBN * SA];
    __shared__ alignas(16) __nv_bfloat16 Bl[GBN * SA];

    const int tid = threadIdx.x;
    const int wid = tid >> 5, lane = tid & 31;
    const int wm = wid & 3, wn = wid >> 2;
    const int col0 = blockIdx.x * GBN;      // col-block fastest -> L2 reuse of X
    const int row0 = blockIdx.y * GBM;
    const int g = lane >> 2, tg = lane & 3;

    // A-load coords (f32): 4 chunks/thread, row ra[l], col ca4[l]
    int ra[4], ca4[4];
#pragma unroll
    for (int l = 0; l < 4; l++) {
        int f = tid + 256 * l;
        ra[l] = f >> 3;
        ca4[l] = (f & 7) << 2;
    }
    // B-load coords: 2 chunks/thread
    int rb[2], kb8[2];
#pragma unroll
    for (int l = 0; l < 2; l++) {
        int f = tid + 256 * l;
        rb[l] = f >> 2;
        kb8[l] = (f & 3) << 3;
    }

    float acc[2][8][4];
#pragma unroll
    for (int a = 0; a < 2; a++)
#pragma unroll
        for (int b = 0; b < 8; b++)
#pragma unroll
            for (int r = 0; r < 4; r++) acc[a][b][r] = 0.f;

    // prologue LDGs (kb = 0)
    float4 av[4];
    uint4 bhv[2], blv[2];
#pragma unroll
    for (int l = 0; l < 4; l++)
        av[l] = *(const float4*)(x + (size_t)(row0 + ra[l]) * DD + ca4[l]);
#pragma unroll
    for (int l = 0; l < 2; l++) {
        size_t gb = (size_t)(col0 + rb[l]) * DD + kb8[l];
        bhv[l] = *(const uint4*)&g_whi[gb];
        blv[l] = *(const uint4*)&g_wlo[gb];
    }

    for (int kb = 0; kb < DD; kb += GBK) {
        // ---- STS: convert & stage current tiles ----
#pragma unroll
        for (int l = 0; l < 4; l++) {
            uint32_t h01, h23, l01, l23;
            split4(av[l], h01, h23, l01, l23);
            *(uint2*)&Ah[ra[l] * SA + ca4[l]] = make_uint2(h01, h23);
            *(uint2*)&Al[ra[l] * SA + ca4[l]] = make_uint2(l01, l23);
        }
#pragma unroll
        for (int l = 0; l < 2; l++) {
            *(uint4*)&Bh[rb[l] * SA + kb8[l]] = bhv[l];
            *(uint4*)&Bl[rb[l] * SA + kb8[l]] = blv[l];
        }
        __syncthreads();

        // ---- prefetch next iteration (covered by MMA phase) ----
        if (kb + GBK < DD) {
#pragma unroll
            for (int l = 0; l < 4; l++)
                av[l] = *(const float4*)(x + (size_t)(row0 + ra[l]) * DD + kb + GBK + ca4[l]);
#pragma unroll
            for (int l = 0; l < 2; l++) {
                size_t gb = (size_t)(col0 + rb[l]) * DD + kb + GBK + kb8[l];
                bhv[l] = *(const uint4*)&g_whi[gb];
                blv[l] = *(const uint4*)&g_wlo[gb];
            }
        }

        // ---- MMA phase ----
#pragma unroll
        for (int ks = 0; ks < GBK; ks += 16) {
            uint32_t afh[2][4], afl[2][4];
            const int kk2 = ks + 2 * tg;
#pragma unroll
            for (int ms = 0; ms < 2; ms++) {
                int rr = wm * 32 + ms * 16 + g;
                afh[ms][0] = *(const uint32_t*)&Ah[rr * SA + kk2];
                afh[ms][1] = *(const uint32_t*)&Ah[(rr + 8) * SA + kk2];
                afh[ms][2] = *(const uint32_t*)&Ah[rr * SA + kk2 + 8];
                afh[ms][3] = *(const uint32_t*)&Ah[(rr + 8) * SA + kk2 + 8];
                afl[ms][0] = *(const uint32_t*)&Al[rr * SA + kk2];
                afl[ms][1] = *(const uint32_t*)&Al[(rr + 8) * SA + kk2];
                afl[ms][2] = *(const uint32_t*)&Al[rr * SA + kk2 + 8];
                afl[ms][3] = *(const uint32_t*)&Al[(rr + 8) * SA + kk2 + 8];
            }
#pragma unroll
            for (int ns = 0; ns < 8; ns++) {
                int nr = wn * 64 + ns * 8 + g;
                uint32_t bh0 = *(const uint32_t*)&Bh[nr * SA + kk2];
                uint32_t bh1 = *(const uint32_t*)&Bh[nr * SA + kk2 + 8];
                uint32_t bl0 = *(const uint32_t*)&Bl[nr * SA + kk2];
                uint32_t bl1 = *(const uint32_t*)&Bl[nr * SA + kk2 + 8];
#pragma unroll
                for (int ms = 0; ms < 2; ms++) {
                    MMA16816(acc[ms][ns], afh[ms], bh0, bh1);
                    MMA16816(acc[ms][ns], afh[ms], bl0, bl1);
                    MMA16816(acc[ms][ns], afl[ms], bh0, bh1);
                }
            }
        }
        __syncthreads();
    }

#pragma unroll
    for (int ms = 0; ms < 2; ms++)
#pragma unroll
        for (int ns = 0; ns < 8; ns++) {
            int m = row0 + wm * 32 + ms * 16 + g;
            int n = col0 + wn * 64 + ns * 8 + tg * 2;
            *(float2*)&g_proj[(size_t)m * NC + n] =
                make_float2(acc[ms][ns][0], acc[ms][ns][1]);
            *(float2*)&g_proj[(size_t)(m + 8) * NC + n] =
                make_float2(acc[ms][ns][2], acc[ms][ns][3]);
        }
}

// ---------------------------------------------------------------------------
// In-chunk Gram: for (chunk,b): G[t*16+u] = k_u . k_t (64-dim dots).
// ---------------------------------------------------------------------------
__global__ __launch_bounds__(256) void gramc_kernel() {
    const int b  = blockIdx.x & 15;
    const int ch = blockIdx.x >> 4;
    const int tid = threadIdx.x;
    __shared__ float Ks[16][68];

    {
        const int s = tid >> 4, j4 = (tid & 15) * 4;
        float4 kv = *(const float4*)(g_proj + ((size_t)(ch * CCH + s) * BB + b) * NC + j4);
        *(float4*)&Ks[s][j4] = kv;
    }
    __syncthreads();

    const int t = tid >> 4, u = tid & 15;
    float acc = 0.f;
#pragma unroll
    for (int j = 0; j < 64; j++) acc = fmaf(Ks[t][j], Ks[u][j], acc);
    g_gramc[((size_t)ch * BB + b) * 256 + t * 16 + u] = acc;
}

// ---------------------------------------------------------------------------
// scanA: chunked sequential gate pass (unchanged from R8 winner).
// ---------------------------------------------------------------------------
__device__ __forceinline__ float fast_tanh(float x) {
    float r;
    asm("tanh.approx.f32 %0, %1;" : "=f"(r) : "f"(x));
    return r;
}

__global__ __launch_bounds__(256) void scanA_kernel(
    const float* __restrict__ S_in,
    const float* __restrict__ dA,
    const float* __restrict__ bA,
    float* __restrict__ out)
{
    const int b  = blockIdx.x >> 2;
    const int qr = blockIdx.x & 3;
    const int i0 = qr * 16;
    const int tid = threadIdx.x;
    const int il = tid >> 4;          // row in block 0..15
    const int i  = i0 + il;           // global row
    const int c  = tid & 15;          // lane in row
    const int j0 = c * 4;

    __shared__ float Kbuf[2][16 * 68];
    __shared__ float Gbuf[2][256];
    __shared__ float Vbuf[2][16][16];   // [buf][s][row]
    __shared__ float Abuf[2][16][16];
    __shared__ float Wsbuf[16][20];

    const int sk = il, jk = j0;
    const int sv = il, iv = c;

    float S0, S1, S2, S3;
    {
        float4 si = *(const float4*)(S_in + ((size_t)b * NN + i) * NN + j0);
        S0 = si.x; S1 = si.y; S2 = si.z; S3 = si.w;
        *(float4*)(g_Scs + ((size_t)b * NN + i) * NN + j0) = si;   // Scs[0]
    }
    float da_ = 0.f, ba_ = 0.f;
    if (c == 0) { da_ = dA[i]; ba_ = bA[i]; }

    // prologue: stage chunk 0 tiles
    {
        float4 kpre = *(const float4*)(g_proj + ((size_t)sk * BB + b) * NC + jk);
        float4 gpre = make_float4(0, 0, 0, 0);
        if (tid < 64) gpre = *(const float4*)(g_gramc + (size_t)b * 256 + tid * 4);
        float vpre = g_proj[((size_t)sv * BB + b) * NC + 64 + i0 + iv];
        float apre = g_proj[((size_t)sv * BB + b) * NC + 192 + i0 + iv];
        *(float4*)&Kbuf[0][sk * 68 + jk] = kpre;
        if (tid < 64) *(float4*)&Gbuf[0][tid * 4] = gpre;
        Vbuf[0][sv][iv] = vpre;
        Abuf[0][sv][iv] = apre;
    }
    __syncthreads();

    // prologue g-dots: g[d] = S_init . k_d (chunk 0)
    float gre[16];
    {
        float pd[16];
#pragma unroll
        for (int d = 0; d < 16; d++) {
            float4 k4 = *(const float4*)&Kbuf[0][d * 68 + j0];
            pd[d] = S0 * k4.x + S1 * k4.y + S2 * k4.z + S3 * k4.w;
        }
#pragma unroll
        for (int m = 1; m < 16; m <<= 1)
#pragma unroll
            for (int d = 0; d < 16; d++)
                pd[d] += __shfl_xor_sync(0xFFFFFFFFu, pd[d], m);
#pragma unroll
        for (int d = 0; d < 16; d++) gre[d] = pd[d];
    }

    for (int ch = 0; ch < NCH; ch++) {
        const int cb = ch & 1, nb = cb ^ 1;

        // issue LDGs for chunk ch+1 (pad-safe)
        const size_t tb1 = (size_t)((ch + 1) * CCH) * BB + b;
        float4 kpre = *(const float4*)(g_proj + (tb1 + (size_t)sk * BB) * NC + jk);
        float4 gpre = make_float4(0, 0, 0, 0);
        if (tid < 64)
            gpre = *(const float4*)(g_gramc + ((size_t)(ch + 1) * BB + b) * 256 + tid * 4);
        float vpre = g_proj[(tb1 + (size_t)sv * BB) * NC + 64 + i0 + iv];
        float apre = g_proj[(tb1 + (size_t)sv * BB) * NC + 192 + i0 + iv];

        // ph2: scalar recursion (one thread per row)
        if (c == 0) {
            float ws[16];
            float pi = 1.f;
            float2* acp = g_ac + ((size_t)(ch * CCH) * BB + b) * NN + i;
#pragma unroll
            for (int s = 0; s < 16; s++) {
                float kc[16];
#pragma unroll
                for (int u4 = 0; u4 < 16; u4 += 4) {
                    float4 f = *(const float4*)&Gbuf[cb][s * 16 + u4];
                    kc[u4] = f.x; kc[u4 + 1] = f.y; kc[u4 + 2] = f.z; kc[u4 + 3] = f.w;
                }
                float a0 = 0.f, a1 = 0.f, a2 = 0.f, a3 = 0.f;
#pragma unroll
                for (int u = 0; u < 16; u++) {
                    if (u < s) {
                        float tmp = ws[u] * kc[u];
                        if ((u & 3) == 0) a0 += tmp;
                        else if ((u & 3) == 1) a1 += tmp;
                        else if ((u & 3) == 2) a2 += tmp;
                        else a3 += tmp;
                    }
                }
                float r = fmaf(pi, gre[s], (a0 + a1) + (a2 + a3));
                float xg = fmaf(da_, r, Abuf[cb][s][il] + ba_);
                float al = fmaf(0.5f, fast_tanh(0.5f * xg), 0.5f);
                float cv = (1.0f - al) * Vbuf[cb][s][il];
                acp[(size_t)s * BB * NN] = make_float2(al, cv);
                pi *= al;
#pragma unroll
                for (int u = 0; u < 16; u++)
                    if (u < s) ws[u] *= al;
                ws[s] = cv;
            }
#pragma unroll
            for (int u = 0; u < 16; u++) Wsbuf[il][u] = ws[u];
            Wsbuf[il][16] = pi;
        }
        __syncthreads();

        // ph3a: stage prefetched tiles
        *(float4*)&Kbuf[nb][sk * 68 + jk] = kpre;
        if (tid < 64) *(float4*)&Gbuf[nb][tid * 4] = gpre;
        Vbuf[nb][sv][iv] = vpre;
        Abuf[nb][sv][iv] = apre;

        // ph3b: S rank-16 update
        {
            float pi2 = Wsbuf[il][16];
            float n0 = pi2 * S0, n1 = pi2 * S1, n2 = pi2 * S2, n3 = pi2 * S3;
#pragma unroll
            for (int s = 0; s < 16; s++) {
                float w = Wsbuf[il][s];
                float4 k4 = *(const float4*)&Kbuf[cb][s * 68 + j0];
                n0 = fmaf(w, k4.x, n0);
                n1 = fmaf(w, k4.y, n1);
                n2 = fmaf(w, k4.z, n2);
                n3 = fmaf(w, k4.w, n3);
            }
            S0 = n0; S1 = n1; S2 = n2; S3 = n3;
            float4 sv4 = make_float4(S0, S1, S2, S3);
            if (ch < NCH - 1)
                *(float4*)(g_Scs + (size_t)(ch + 1) * BB * NN * NN
                           + ((size_t)b * NN + i) * NN + j0) = sv4;
            else
                *(float4*)(out + (size_t)TT * BB * NN
                           + ((size_t)b * NN + i) * NN + j0) = sv4;
        }
        __syncthreads();

        // ph3c: g-dots for chunk ch+1
        {
            float pd[16];
#pragma unroll
            for (int d = 0; d < 16; d++) {
                float4 k4 = *(const float4*)&Kbuf[nb][d * 68 + j0];
                pd[d] = S0 * k4.x + S1 * k4.y + S2 * k4.z + S3 * k4.w;
            }
#pragma unroll
            for (int m = 1; m < 16; m <<= 1)
#pragma unroll
                for (int d = 0; d < 16; d++)
                    pd[d] += __shfl_xor_sync(0xFFFFFFFFu, pd[d], m);
#pragma unroll
            for (int d = 0; d < 16; d++) gre[d] = pd[d];
        }
    }
}

// ---------------------------------------------------------------------------
// b3: outputs. Block per (b,chunk), 64 threads (thread = row i).
// ---------------------------------------------------------------------------
__global__ __launch_bounds__(64) void b3_out(float* __restrict__ out) {
    const int b  = blockIdx.x & 15;
    const int ch = blockIdx.x >> 4;
    const int tid = threadIdx.x;          // = i

    __shared__ float Ks[CCH][68];
    __shared__ float Qs[CCH][68];
    __shared__ float Dm[CCH][CCH];

#pragma unroll
    for (int s = 0; s < CCH; s++) {
        const float* P = g_proj + ((size_t)(ch * CCH + s) * BB + b) * NC;
        Ks[s][tid] = P[tid];
        Qs[s][tid] = P[128 + tid];
    }
    __syncthreads();

#pragma unroll
    for (int e = 0; e < 4; e++) {
        int id = tid * 4 + e;
        int s = id >> 4, t = id & 15;
        float a = 0.f;
#pragma unroll
        for (int j = 0; j < NN; j++) a = fmaf(Ks[s][j], Qs[t][j], a);
        Dm[s][t] = a;
    }
    __syncthreads();

    float Sr[NN];
    {
        const float* P = g_Scs + (size_t)ch * BB * NN * NN + ((size_t)b * NN + tid) * NN;
#pragma unroll
        for (int j = 0; j < NN; j += 4) {
            float4 f = *(const float4*)(P + j);
            Sr[j] = f.x; Sr[j + 1] = f.y; Sr[j + 2] = f.z; Sr[j + 3] = f.w;
        }
    }

    float gt[CCH];
#pragma unroll
    for (int t = 0; t < CCH; t++) {
        float a = 0.f;
#pragma unroll
        for (int j = 0; j < NN; j++) a = fmaf(Sr[j], Qs[t][j], a);
        gt[t] = a;
    }

    float al[CCH], cc[CCH];
#pragma unroll
    for (int s = 0; s < CCH; s++) {
        float2 v = g_ac[((size_t)(ch * CCH + s) * BB + b) * NN + tid];
        al[s] = v.x; cc[s] = v.y;
    }

    float w[CCH];
    float pi = 1.f;
#pragma unroll
    for (int t = 0; t < CCH; t++) {
        float a = al[t];
        pi *= a;
#pragma unroll
        for (int s = 0; s < CCH; s++)
            if (s < t) w[s] *= a;
        w[t] = cc[t];
        float o = pi * gt[t];
#pragma unroll
        for (int s = 0; s < CCH; s++)
            if (s <= t) o = fmaf(w[s], Dm[s][t], o);
        float sg = fmaf(0.5f, fast_tanh(0.5f * o), 0.5f);
        out[((size_t)(ch * CCH + t) * BB + b) * NN + tid] = o * o * sg;
    }
}

extern "C" void kernel_launch(void* const* d_in, const int* in_sizes, int n_in,
                              void* d_out, int out_size) {
    const float* x  = (const float*)d_in[0];
    const float* S  = (const float*)d_in[1];
    const float* Wk = (const float*)d_in[2];
    const float* Wv = (const float*)d_in[3];
    const float* Wq = (const float*)d_in[4];
    const float* Wa = (const float*)d_in[5];
    const float* da = (const float*)d_in[6];
    const float* ba = (const float*)d_in[7];
    float* out = (float*)d_out;

    convert_w<<<NC * DD / (256 * 4), 256>>>(Wk, Wv, Wq, Wa);
    dim3 ggrid(NC / GBN, MT / GBM);            // col-block fastest
    mma_gemm<<<ggrid, 256>>>(x);
    gramc_kernel<<<NCH * BB, 256>>>();
    scanA_kernel<<<BB * 4, 256>>>(S, da, ba, out);
    b3_out<<<NCH * BB, 64>>>(out);
}

// round 11
// speedup vs baseline: 1.8354x; 1.1136x over previous
#include <cuda_runtime.h>
#include <cuda_bf16.h>
#include <cstdint>

#define TT 2048
#define BB 16
#define DD 1024
#define NN 64
#define MT (TT * BB)      // 32768 rows
#define NC 256            // k|v|q|a packed columns
#define PAD_T 32          // zero padding time-steps (device globals zero-init)
#define CCH 16            // chunk size
#define NCH (TT / CCH)    // 128 chunks

// ------------------------- device scratch (no allocs allowed) ---------------
__device__ float g_proj[(size_t)(MT + PAD_T * BB) * NC];       // + pad (zero)
__device__ float g_gramc[(size_t)(NCH + 2) * BB * 256];        // in-chunk k-Gram (+pad)
__device__ float2 g_ac[(size_t)MT * NN];                       // (alpha, cc)
__device__ float g_Scs[(size_t)NCH * BB * NN * NN];            // chunk-start states
__device__ __nv_bfloat16 g_whi[(size_t)NC * DD];
__device__ __nv_bfloat16 g_wlo[(size_t)NC * DD];

// ---------------------------------------------------------------------------
// Convert W (4 matrices stacked: k|v|q|a) -> bf16 hi/lo
// ---------------------------------------------------------------------------
__global__ __launch_bounds__(256) void convert_w(
    const float* __restrict__ Wk, const float* __restrict__ Wv,
    const float* __restrict__ Wq, const float* __restrict__ Wa)
{
    int e4 = blockIdx.x * 256 + threadIdx.x;
    int base = e4 * 4;
    int row = base >> 10;
    int colk = base & 1023;
    int cb = row >> 6, n = row & 63;
    const float* W = (cb == 0) ? Wk : (cb == 1) ? Wv : (cb == 2) ? Wq : Wa;
    float4 v = *(const float4*)(W + (size_t)n * DD + colk);
    __nv_bfloat16 h0 = __float2bfloat16(v.x);
    __nv_bfloat16 h1 = __float2bfloat16(v.y);
    __nv_bfloat16 h2 = __float2bfloat16(v.z);
    __nv_bfloat16 h3 = __float2bfloat16(v.w);
    __nv_bfloat16 l0 = __float2bfloat16(v.x - __bfloat162float(h0));
    __nv_bfloat16 l1 = __float2bfloat16(v.y - __bfloat162float(h1));
    __nv_bfloat16 l2 = __float2bfloat16(v.z - __bfloat162float(h2));
    __nv_bfloat16 l3 = __float2bfloat16(v.w - __bfloat162float(h3));
    __nv_bfloat162 hp0 = __halves2bfloat162(h0, h1);
    __nv_bfloat162 hp1 = __halves2bfloat162(h2, h3);
    __nv_bfloat162 lp0 = __halves2bfloat162(l0, l1);
    __nv_bfloat162 lp1 = __halves2bfloat162(l2, l3);
    *(uint2*)&g_whi[(size_t)row * DD + colk] = make_uint2(*(uint32_t*)&hp0, *(uint32_t*)&hp1);
    *(uint2*)&g_wlo[(size_t)row * DD + colk] = make_uint2(*(uint32_t*)&lp0, *(uint32_t*)&lp1);
}

// ---------------------------------------------------------------------------
// Fused tensor-core GEMM (unchanged from R9 winner).
// ---------------------------------------------------------------------------
#define GBM 128
#define GBN 128
#define GBK 32
#define SA  40

#define MMA16816(d, a, b0v, b1v)                                              \
    asm volatile("mma.sync.aligned.m16n8k16.row.col.f32.bf16.bf16.f32 "       \
                 "{%0,%1,%2,%3}, {%4,%5,%6,%7}, {%8,%9}, {%0,%1,%2,%3};"      \
                 : "+f"(d[0]), "+f"(d[1]), "+f"(d[2]), "+f"(d[3])             \
                 : "r"(a[0]), "r"(a[1]), "r"(a[2]), "r"(a[3]),                \
                   "r"(b0v), "r"(b1v));

__device__ __forceinline__ void split4(float4 v, uint32_t& h01, uint32_t& h23,
                                       uint32_t& l01, uint32_t& l23) {
    __nv_bfloat16 h0 = __float2bfloat16(v.x);
    __nv_bfloat16 h1 = __float2bfloat16(v.y);
    __nv_bfloat16 h2 = __float2bfloat16(v.z);
    __nv_bfloat16 h3 = __float2bfloat16(v.w);
    __nv_bfloat16 l0 = __float2bfloat16(v.x - __bfloat162float(h0));
    __nv_bfloat16 l1 = __float2bfloat16(v.y - __bfloat162float(h1));
    __nv_bfloat16 l2 = __float2bfloat16(v.z - __bfloat162float(h2));
    __nv_bfloat16 l3 = __float2bfloat16(v.w - __bfloat162float(h3));
    __nv_bfloat162 hp0 = __halves2bfloat162(h0, h1);
    __nv_bfloat162 hp1 = __halves2bfloat162(h2, h3);
    __nv_bfloat162 lp0 = __halves2bfloat162(l0, l1);
    __nv_bfloat162 lp1 = __halves2bfloat162(l2, l3);
    h01 = *(uint32_t*)&hp0; h23 = *(uint32_t*)&hp1;
    l01 = *(uint32_t*)&lp0; l23 = *(uint32_t*)&lp1;
}

__global__ __launch_bounds__(256) void mma_gemm(const float* __restrict__ x) {
    __shared__ alignas(16) __nv_bfloat16 Ah[GBM * SA];
    __shared__ alignas(16) __nv_bfloat16 Al[GBM * SA];
    __shared__ alignas(16) __nv_bfloat16 Bh[GBN * SA];
    __shared__ alignas(16) __nv_bfloat16 Bl[GBN * SA];

    const int tid = threadIdx.x;
    const int wid = tid >> 5, lane = tid & 31;
    const int wm = wid & 3, wn = wid >> 2;
    const int col0 = blockIdx.x * GBN;
    const int row0 = blockIdx.y * GBM;
    const int g = lane >> 2, tg = lane & 3;

    int ra[4], ca4[4];
#pragma unroll
    for (int l = 0; l < 4; l++) {
        int f = tid + 256 * l;
        ra[l] = f >> 3;
        ca4[l] = (f & 7) << 2;
    }
    int rb[2], kb8[2];
#pragma unroll
    for (int l = 0; l < 2; l++) {
        int f = tid + 256 * l;
        rb[l] = f >> 2;
        kb8[l] = (f & 3) << 3;
    }

    float acc[2][8][4];
#pragma unroll
    for (int a = 0; a < 2; a++)
#pragma unroll
        for (int b = 0; b < 8; b++)
#pragma unroll
            for (int r = 0; r < 4; r++) acc[a][b][r] = 0.f;

    float4 av[4];
    uint4 bhv[2], blv[2];
#pragma unroll
    for (int l = 0; l < 4; l++)
        av[l] = *(const float4*)(x + (size_t)(row0 + ra[l]) * DD + ca4[l]);
#pragma unroll
    for (int l = 0; l < 2; l++) {
        size_t gb = (size_t)(col0 + rb[l]) * DD + kb8[l];
        bhv[l] = *(const uint4*)&g_whi[gb];
        blv[l] = *(const uint4*)&g_wlo[gb];
    }

    for (int kb = 0; kb < DD; kb += GBK) {
#pragma unroll
        for (int l = 0; l < 4; l++) {
            uint32_t h01, h23, l01, l23;
            split4(av[l], h01, h23, l01, l23);
            *(uint2*)&Ah[ra[l] * SA + ca4[l]] = make_uint2(h01, h23);
            *(uint2*)&Al[ra[l] * SA + ca4[l]] = make_uint2(l01, l23);
        }
#pragma unroll
        for (int l = 0; l < 2; l++) {
            *(uint4*)&Bh[rb[l] * SA + kb8[l]] = bhv[l];
            *(uint4*)&Bl[rb[l] * SA + kb8[l]] = blv[l];
        }
        __syncthreads();

        if (kb + GBK < DD) {
#pragma unroll
            for (int l = 0; l < 4; l++)
                av[l] = *(const float4*)(x + (size_t)(row0 + ra[l]) * DD + kb + GBK + ca4[l]);
#pragma unroll
            for (int l = 0; l < 2; l++) {
                size_t gb = (size_t)(col0 + rb[l]) * DD + kb + GBK + kb8[l];
                bhv[l] = *(const uint4*)&g_whi[gb];
                blv[l] = *(const uint4*)&g_wlo[gb];
            }
        }

#pragma unroll
        for (int ks = 0; ks < GBK; ks += 16) {
            uint32_t afh[2][4], afl[2][4];
            const int kk2 = ks + 2 * tg;
#pragma unroll
            for (int ms = 0; ms < 2; ms++) {
                int rr = wm * 32 + ms * 16 + g;
                afh[ms][0] = *(const uint32_t*)&Ah[rr * SA + kk2];
                afh[ms][1] = *(const uint32_t*)&Ah[(rr + 8) * SA + kk2];
                afh[ms][2] = *(const uint32_t*)&Ah[rr * SA + kk2 + 8];
                afh[ms][3] = *(const uint32_t*)&Ah[(rr + 8) * SA + kk2 + 8];
                afl[ms][0] = *(const uint32_t*)&Al[rr * SA + kk2];
                afl[ms][1] = *(const uint32_t*)&Al[(rr + 8) * SA + kk2];
                afl[ms][2] = *(const uint32_t*)&Al[rr * SA + kk2 + 8];
                afl[ms][3] = *(const uint32_t*)&Al[(rr + 8) * SA + kk2 + 8];
            }
#pragma unroll
            for (int ns = 0; ns < 8; ns++) {
                int nr = wn * 64 + ns * 8 + g;
                uint32_t bh0 = *(const uint32_t*)&Bh[nr * SA + kk2];
                uint32_t bh1 = *(const uint32_t*)&Bh[nr * SA + kk2 + 8];
                uint32_t bl0 = *(const uint32_t*)&Bl[nr * SA + kk2];
                uint32_t bl1 = *(const uint32_t*)&Bl[nr * SA + kk2 + 8];
#pragma unroll
                for (int ms = 0; ms < 2; ms++) {
                    MMA16816(acc[ms][ns], afh[ms], bh0, bh1);
                    MMA16816(acc[ms][ns], afh[ms], bl0, bl1);
                    MMA16816(acc[ms][ns], afl[ms], bh0, bh1);
                }
            }
        }
        __syncthreads();
    }

#pragma unroll
    for (int ms = 0; ms < 2; ms++)
#pragma unroll
        for (int ns = 0; ns < 8; ns++) {
            int m = row0 + wm * 32 + ms * 16 + g;
            int n = col0 + wn * 64 + ns * 8 + tg * 2;
            *(float2*)&g_proj[(size_t)m * NC + n] =
                make_float2(acc[ms][ns][0], acc[ms][ns][1]);
            *(float2*)&g_proj[(size_t)(m + 8) * NC + n] =
                make_float2(acc[ms][ns][2], acc[ms][ns][3]);
        }
}

// ---------------------------------------------------------------------------
// In-chunk Gram: for (chunk,b): G[t*16+u] = k_t . k_u (symmetric).
// ---------------------------------------------------------------------------
__global__ __launch_bounds__(256) void gramc_kernel() {
    const int b  = blockIdx.x & 15;
    const int ch = blockIdx.x >> 4;
    const int tid = threadIdx.x;
    __shared__ float Ks[16][68];

    {
        const int s = tid >> 4, j4 = (tid & 15) * 4;
        float4 kv = *(const float4*)(g_proj + ((size_t)(ch * CCH + s) * BB + b) * NC + j4);
        *(float4*)&Ks[s][j4] = kv;
    }
    __syncthreads();

    const int t = tid >> 4, u = tid & 15;
    float acc = 0.f;
#pragma unroll
    for (int j = 0; j < 64; j++) acc = fmaf(Ks[t][j], Ks[u][j], acc);
    g_gramc[((size_t)ch * BB + b) * 256 + t * 16 + u] = acc;
}

// ---------------------------------------------------------------------------
// scanA v2: chunked, with
//  - ph2 on ONE warp (row = lane 0..15), short critical chain:
//      r_s = fma(al_{s-1}, C, D), C/D precomputed from pre-update ws/pi.
//  - ph3c g-dots as a 16x16 smem matmul (no shuffles): thread (il,c) computes
//      Gre[il][c] = sum_j Sbuf[il][j] * Knext[c][j].
// 64 blocks x 256 threads. 3 bars/chunk.
// ---------------------------------------------------------------------------
__device__ __forceinline__ float fast_tanh(float x) {
    float r;
    asm("tanh.approx.f32 %0, %1;" : "=f"(r) : "f"(x));
    return r;
}

__global__ __launch_bounds__(256) void scanA_kernel(
    const float* __restrict__ S_in,
    const float* __restrict__ dA,
    const float* __restrict__ bA,
    float* __restrict__ out)
{
    const int b  = blockIdx.x >> 2;
    const int qr = blockIdx.x & 3;
    const int i0 = qr * 16;
    const int tid = threadIdx.x;
    const int il = tid >> 4;          // row in block 0..15
    const int i  = i0 + il;           // global row
    const int c  = tid & 15;          // lane in row
    const int j0 = c * 4;

    __shared__ float Kbuf[2][16 * 68];
    __shared__ float Gbuf[2][256];
    __shared__ float Vbuf[2][16][16];   // [buf][s][row]
    __shared__ float Abuf[2][16][16];
    __shared__ float Wsbuf[16][20];     // [row][ws0..15, pi]
    __shared__ float Grebuf[16][20];    // [row][d]
    __shared__ float Sbuf[16][68];      // [row][j]

    const int sk = il, jk = j0;
    const int sv = il, iv = c;

    float S0, S1, S2, S3;
    {
        float4 si = *(const float4*)(S_in + ((size_t)b * NN + i) * NN + j0);
        S0 = si.x; S1 = si.y; S2 = si.z; S3 = si.w;
        *(float4*)(g_Scs + ((size_t)b * NN + i) * NN + j0) = si;   // Scs[0]
        *(float4*)&Sbuf[il][j0] = si;
    }
    float dah = 0.f, bah = 0.f;
    if (tid < 16) {
        dah = 0.5f * dA[i0 + tid];
        bah = 0.5f * bA[i0 + tid];
    }

    // ---- prologue: stage chunk 0 tiles into buf 0 ----
    {
        float4 kpre = *(const float4*)(g_proj + ((size_t)sk * BB + b) * NC + jk);
        float4 gpre = make_float4(0, 0, 0, 0);
        if (tid < 64) gpre = *(const float4*)(g_gramc + (size_t)b * 256 + tid * 4);
        float vpre = g_proj[((size_t)sv * BB + b) * NC + 64 + i0 + iv];
        float apre = g_proj[((size_t)sv * BB + b) * NC + 192 + i0 + iv];
        *(float4*)&Kbuf[0][sk * 68 + jk] = kpre;
        if (tid < 64) *(float4*)&Gbuf[0][tid * 4] = gpre;
        Vbuf[0][sv][iv] = vpre;
        Abuf[0][sv][iv] = apre;
    }
    __syncthreads();

    // ---- prologue Gre: Gre[il][c] = S_init[il] . k_c (chunk 0) ----
    {
        float acc = 0.f;
#pragma unroll
        for (int j4 = 0; j4 < 64; j4 += 4) {
            float4 sv4 = *(const float4*)&Sbuf[il][j4];
            float4 kv4 = *(const float4*)&Kbuf[0][c * 68 + j4];
            acc = fmaf(sv4.x, kv4.x, acc);
            acc = fmaf(sv4.y, kv4.y, acc);
            acc = fmaf(sv4.z, kv4.z, acc);
            acc = fmaf(sv4.w, kv4.w, acc);
        }
        Grebuf[il][c] = acc;
    }

    // ---- prologue LDG chunk 1 -> regs ----
    float4 kpre, gpre;
    float vpre, apre;
    {
        const size_t tb1 = (size_t)CCH * BB + b;
        kpre = *(const float4*)(g_proj + (tb1 + (size_t)sk * BB) * NC + jk);
        gpre = make_float4(0, 0, 0, 0);
        if (tid < 64)
            gpre = *(const float4*)(g_gramc + ((size_t)1 * BB + b) * 256 + tid * 4);
        vpre = g_proj[(tb1 + (size_t)sv * BB) * NC + 64 + i0 + iv];
        apre = g_proj[(tb1 + (size_t)sv * BB) * NC + 192 + i0 + iv];
    }
    __syncthreads();

    for (int ch = 0; ch < NCH; ch++) {
        const int cb = ch & 1, nb = cb ^ 1;

        // ---- stage regs (chunk ch+1) into buffer nb ----
        *(float4*)&Kbuf[nb][sk * 68 + jk] = kpre;
        if (tid < 64) *(float4*)&Gbuf[nb][tid * 4] = gpre;
        Vbuf[nb][sv][iv] = vpre;
        Abuf[nb][sv][iv] = apre;

        // ---- issue LDGs for chunk ch+2 (pad-safe, PAD_T=32) ----
        {
            const size_t tb2 = (size_t)((ch + 2) * CCH) * BB + b;
            kpre = *(const float4*)(g_proj + (tb2 + (size_t)sk * BB) * NC + jk);
            if (tid < 64)
                gpre = *(const float4*)(g_gramc + ((size_t)(ch + 2) * BB + b) * 256 + tid * 4);
            vpre = g_proj[(tb2 + (size_t)sv * BB) * NC + 64 + i0 + iv];
            apre = g_proj[(tb2 + (size_t)sv * BB) * NC + 192 + i0 + iv];
        }

        // ---- ph2: single-warp scalar recursion (lane = row) ----
        if (tid < 16) {
            const int r = tid;
            float gre[16];
#pragma unroll
            for (int d4 = 0; d4 < 16; d4 += 4) {
                float4 f = *(const float4*)&Grebuf[r][d4];
                gre[d4] = f.x; gre[d4 + 1] = f.y; gre[d4 + 2] = f.z; gre[d4 + 3] = f.w;
            }
            float ws[16];
            float pi = 1.f, al_prev = 1.f, vt_prev = 0.f;
            float2* acp = g_ac + ((size_t)(ch * CCH) * BB + b) * NN + i0 + r;

#pragma unroll
            for (int s = 0; s < 16; s++) {
                float kc[16];
#pragma unroll
                for (int u4 = 0; u4 < 16; u4 += 4) {
                    float4 f = *(const float4*)&Gbuf[cb][s * 16 + u4];
                    kc[u4] = f.x; kc[u4 + 1] = f.y; kc[u4 + 2] = f.z; kc[u4 + 3] = f.w;
                }
                // A from PRE-update ws/pi (state through s-2)
                float a0 = 0.f, a1 = 0.f, a2 = 0.f, a3 = 0.f;
#pragma unroll
                for (int u = 0; u < 16; u++) {
                    if (u <= s - 2) {
                        float t2 = ws[u] * kc[u];
                        if ((u & 3) == 0) a0 += t2;
                        else if ((u & 3) == 1) a1 += t2;
                        else if ((u & 3) == 2) a2 += t2;
                        else a3 += t2;
                    }
                }
                float A = fmaf(pi, gre[s], (a0 + a1) + (a2 + a3));
                float B = (s >= 1) ? kc[s - 1] : 0.f;
                float C = fmaf(-vt_prev, B, A);
                float D = vt_prev * B;
                // ---- critical chain ----
                float rr = fmaf(al_prev, C, D);
                float xg = fmaf(dah, rr, fmaf(0.5f, Abuf[cb][s][r], bah));
                float al = fmaf(0.5f, fast_tanh(xg), 0.5f);
                // ---- off-chain updates with al_prev ----
                if (s >= 1) {
                    pi *= al_prev;
#pragma unroll
                    for (int u = 0; u < 16; u++)
                        if (u <= s - 2) ws[u] *= al_prev;
                    float cvp = fmaf(-al_prev, vt_prev, vt_prev);
                    ws[s - 1] = cvp;
                    acp[(size_t)(s - 1) * BB * NN] = make_float2(al_prev, cvp);
                }
                al_prev = al;
                vt_prev = Vbuf[cb][s][r];
            }
            // epilogue: apply al_15
            pi *= al_prev;
#pragma unroll
            for (int u = 0; u < 15; u++) ws[u] *= al_prev;
            float cvl = fmaf(-al_prev, vt_prev, vt_prev);
            ws[15] = cvl;
            acp[(size_t)15 * BB * NN] = make_float2(al_prev, cvl);
#pragma unroll
            for (int u4 = 0; u4 < 16; u4 += 4)
                *(float4*)&Wsbuf[r][u4] =
                    make_float4(ws[u4], ws[u4 + 1], ws[u4 + 2], ws[u4 + 3]);
            Wsbuf[r][16] = pi;
        }
        __syncthreads();   // Wsbuf + nb staging visible

        // ---- ph3b: S rank-16 update; write Sbuf + Scs/out ----
        {
            float pi2 = Wsbuf[il][16];
            float n0 = pi2 * S0, n1 = pi2 * S1, n2 = pi2 * S2, n3 = pi2 * S3;
#pragma unroll
            for (int s = 0; s < 16; s++) {
                float w = Wsbuf[il][s];
                float4 k4 = *(const float4*)&Kbuf[cb][s * 68 + j0];
                n0 = fmaf(w, k4.x, n0);
                n1 = fmaf(w, k4.y, n1);
                n2 = fmaf(w, k4.z, n2);
                n3 = fmaf(w, k4.w, n3);
            }
            S0 = n0; S1 = n1; S2 = n2; S3 = n3;
            float4 sv4 = make_float4(S0, S1, S2, S3);
            *(float4*)&Sbuf[il][j0] = sv4;
            if (ch < NCH - 1)
                *(float4*)(g_Scs + (size_t)(ch + 1) * BB * NN * NN
                           + ((size_t)b * NN + i) * NN + j0) = sv4;
            else
                *(float4*)(out + (size_t)TT * BB * NN
                           + ((size_t)b * NN + i) * NN + j0) = sv4;
        }
        __syncthreads();   // Sbuf visible

        // ---- ph3c: Gre[il][c] = Sbuf[il] . Knext[c] (no shuffles) ----
        {
            float acc = 0.f;
#pragma unroll
            for (int j4 = 0; j4 < 64; j4 += 4) {
                float4 sv4 = *(const float4*)&Sbuf[il][j4];
                float4 kv4 = *(const float4*)&Kbuf[nb][c * 68 + j4];
                acc = fmaf(sv4.x, kv4.x, acc);
                acc = fmaf(sv4.y, kv4.y, acc);
                acc = fmaf(sv4.z, kv4.z, acc);
                acc = fmaf(sv4.w, kv4.w, acc);
            }
            Grebuf[il][c] = acc;
        }
        __syncthreads();   // Grebuf visible for next ph2
    }
}

// ---------------------------------------------------------------------------
// b3: outputs. Block per (b,chunk), 64 threads (thread = row i).
// ---------------------------------------------------------------------------
__global__ __launch_bounds__(64) void b3_out(float* __restrict__ out) {
    const int b  = blockIdx.x & 15;
    const int ch = blockIdx.x >> 4;
    const int tid = threadIdx.x;          // = i

    __shared__ float Ks[CCH][68];
    __shared__ float Qs[CCH][68];
    __shared__ float Dm[CCH][CCH];

#pragma unroll
    for (int s = 0; s < CCH; s++) {
        const float* P = g_proj + ((size_t)(ch * CCH + s) * BB + b) * NC;
        Ks[s][tid] = P[tid];
        Qs[s][tid] = P[128 + tid];
    }
    __syncthreads();

#pragma unroll
    for (int e = 0; e < 4; e++) {
        int id = tid * 4 + e;
        int s = id >> 4, t = id & 15;
        float a = 0.f;
#pragma unroll
        for (int j = 0; j < NN; j++) a = fmaf(Ks[s][j], Qs[t][j], a);
        Dm[s][t] = a;
    }
    __syncthreads();

    float Sr[NN];
    {
        const float* P = g_Scs + (size_t)ch * BB * NN * NN + ((size_t)b * NN + tid) * NN;
#pragma unroll
        for (int j = 0; j < NN; j += 4) {
            float4 f = *(const float4*)(P + j);
            Sr[j] = f.x; Sr[j + 1] = f.y; Sr[j + 2] = f.z; Sr[j + 3] = f.w;
        }
    }

    float gt[CCH];
#pragma unroll
    for (int t = 0; t < CCH; t++) {
        float a = 0.f;
#pragma unroll
        for (int j = 0; j < NN; j++) a = fmaf(Sr[j], Qs[t][j], a);
        gt[t] = a;
    }

    float al[CCH], cc[CCH];
#pragma unroll
    for (int s = 0; s < CCH; s++) {
        float2 v = g_ac[((size_t)(ch * CCH + s) * BB + b) * NN + tid];
        al[s] = v.x; cc[s] = v.y;
    }

    float w[CCH];
    float pi = 1.f;
#pragma unroll
    for (int t = 0; t < CCH; t++) {
        float a = al[t];
        pi *= a;
#pragma unroll
        for (int s = 0; s < CCH; s++)
            if (s < t) w[s] *= a;
        w[t] = cc[t];
        float o = pi * gt[t];
#pragma unroll
        for (int s = 0; s < CCH; s++)
            if (s <= t) o = fmaf(w[s], Dm[s][t], o);
        float sg = fmaf(0.5f, fast_tanh(0.5f * o), 0.5f);
        out[((size_t)(ch * CCH + t) * BB + b) * NN + tid] = o * o * sg;
    }
}

extern "C" void kernel_launch(void* const* d_in, const int* in_sizes, int n_in,
                              void* d_out, int out_size) {
    const float* x  = (const float*)d_in[0];
    const float* S  = (const float*)d_in[1];
    const float* Wk = (const float*)d_in[2];
    const float* Wv = (const float*)d_in[3];
    const float* Wq = (const float*)d_in[4];
    const float* Wa = (const float*)d_in[5];
    const float* da = (const float*)d_in[6];
    const float* ba = (const float*)d_in[7];
    float* out = (float*)d_out;

    convert_w<<<NC * DD / (256 * 4), 256>>>(Wk, Wv, Wq, Wa);
    dim3 ggrid(NC / GBN, MT / GBM);
    mma_gemm<<<ggrid, 256>>>(x);
    gramc_kernel<<<NCH * BB, 256>>>();
    scanA_kernel<<<BB * 4, 256>>>(S, da, ba, out);
    b3_out<<<NCH * BB, 64>>>(out);
}

// round 12
// speedup vs baseline: 1.9200x; 1.0461x over previous
#include <cuda_runtime.h>
#include <cuda_bf16.h>
#include <cstdint>

#define TT 2048
#define BB 16
#define DD 1024
#define NN 64
#define MT (TT * BB)      // 32768 rows
#define NC 256            // k|v|q|a packed columns
#define PAD_T 32          // zero padding time-steps (device globals zero-init)
#define CCH 16            // chunk size
#define NCH (TT / CCH)    // 128 chunks

// ------------------------- device scratch (no allocs allowed) ---------------
__device__ float g_proj[(size_t)(MT + PAD_T * BB) * NC];       // + pad (zero)
__device__ float g_gramc[(size_t)(NCH + 2) * BB * 256];        // in-chunk k-Gram (+pad)
__device__ float2 g_ac[(size_t)MT * NN];                       // (alpha, cc)
__device__ float g_Scs[(size_t)NCH * BB * NN * NN];            // chunk-start states
__device__ __nv_bfloat16 g_whi[(size_t)NC * DD];
__device__ __nv_bfloat16 g_wlo[(size_t)NC * DD];

// ---------------------------------------------------------------------------
// Convert W (4 matrices stacked: k|v|q|a) -> bf16 hi/lo
// ---------------------------------------------------------------------------
__global__ __launch_bounds__(256) void convert_w(
    const float* __restrict__ Wk, const float* __restrict__ Wv,
    const float* __restrict__ Wq, const float* __restrict__ Wa)
{
    int e4 = blockIdx.x * 256 + threadIdx.x;
    int base = e4 * 4;
    int row = base >> 10;
    int colk = base & 1023;
    int cb = row >> 6, n = row & 63;
    const float* W = (cb == 0) ? Wk : (cb == 1) ? Wv : (cb == 2) ? Wq : Wa;
    float4 v = *(const float4*)(W + (size_t)n * DD + colk);
    __nv_bfloat16 h0 = __float2bfloat16(v.x);
    __nv_bfloat16 h1 = __float2bfloat16(v.y);
    __nv_bfloat16 h2 = __float2bfloat16(v.z);
    __nv_bfloat16 h3 = __float2bfloat16(v.w);
    __nv_bfloat16 l0 = __float2bfloat16(v.x - __bfloat162float(h0));
    __nv_bfloat16 l1 = __float2bfloat16(v.y - __bfloat162float(h1));
    __nv_bfloat16 l2 = __float2bfloat16(v.z - __bfloat162float(h2));
    __nv_bfloat16 l3 = __float2bfloat16(v.w - __bfloat162float(h3));
    __nv_bfloat162 hp0 = __halves2bfloat162(h0, h1);
    __nv_bfloat162 hp1 = __halves2bfloat162(h2, h3);
    __nv_bfloat162 lp0 = __halves2bfloat162(l0, l1);
    __nv_bfloat162 lp1 = __halves2bfloat162(l2, l3);
    *(uint2*)&g_whi[(size_t)row * DD + colk] = make_uint2(*(uint32_t*)&hp0, *(uint32_t*)&hp1);
    *(uint2*)&g_wlo[(size_t)row * DD + colk] = make_uint2(*(uint32_t*)&lp0, *(uint32_t*)&lp1);
}

// ---------------------------------------------------------------------------
// Fused tensor-core GEMM (unchanged from R9 winner).
// ---------------------------------------------------------------------------
#define GBM 128
#define GBN 128
#define GBK 32
#define SA  40

#define MMA16816(d, a, b0v, b1v)                                              \
    asm volatile("mma.sync.aligned.m16n8k16.row.col.f32.bf16.bf16.f32 "       \
                 "{%0,%1,%2,%3}, {%4,%5,%6,%7}, {%8,%9}, {%0,%1,%2,%3};"      \
                 : "+f"(d[0]), "+f"(d[1]), "+f"(d[2]), "+f"(d[3])             \
                 : "r"(a[0]), "r"(a[1]), "r"(a[2]), "r"(a[3]),                \
                   "r"(b0v), "r"(b1v));

__device__ __forceinline__ void split4(float4 v, uint32_t& h01, uint32_t& h23,
                                       uint32_t& l01, uint32_t& l23) {
    __nv_bfloat16 h0 = __float2bfloat16(v.x);
    __nv_bfloat16 h1 = __float2bfloat16(v.y);
    __nv_bfloat16 h2 = __float2bfloat16(v.z);
    __nv_bfloat16 h3 = __float2bfloat16(v.w);
    __nv_bfloat16 l0 = __float2bfloat16(v.x - __bfloat162float(h0));
    __nv_bfloat16 l1 = __float2bfloat16(v.y - __bfloat162float(h1));
    __nv_bfloat16 l2 = __float2bfloat16(v.z - __bfloat162float(h2));
    __nv_bfloat16 l3 = __float2bfloat16(v.w - __bfloat162float(h3));
    __nv_bfloat162 hp0 = __halves2bfloat162(h0, h1);
    __nv_bfloat162 hp1 = __halves2bfloat162(h2, h3);
    __nv_bfloat162 lp0 = __halves2bfloat162(l0, l1);
    __nv_bfloat162 lp1 = __halves2bfloat162(l2, l3);
    h01 = *(uint32_t*)&hp0; h23 = *(uint32_t*)&hp1;
    l01 = *(uint32_t*)&lp0; l23 = *(uint32_t*)&lp1;
}

__global__ __launch_bounds__(256) void mma_gemm(const float* __restrict__ x) {
    __shared__ alignas(16) __nv_bfloat16 Ah[GBM * SA];
    __shared__ alignas(16) __nv_bfloat16 Al[GBM * SA];
    __shared__ alignas(16) __nv_bfloat16 Bh[GBN * SA];
    __shared__ alignas(16) __nv_bfloat16 Bl[GBN * SA];

    const int tid = threadIdx.x;
    const int wid = tid >> 5, lane = tid & 31;
    const int wm = wid & 3, wn = wid >> 2;
    const int col0 = blockIdx.x * GBN;
    const int row0 = blockIdx.y * GBM;
    const int g = lane >> 2, tg = lane & 3;

    int ra[4], ca4[4];
#pragma unroll
    for (int l = 0; l < 4; l++) {
        int f = tid + 256 * l;
        ra[l] = f >> 3;
        ca4[l] = (f & 7) << 2;
    }
    int rb[2], kb8[2];
#pragma unroll
    for (int l = 0; l < 2; l++) {
        int f = tid + 256 * l;
        rb[l] = f >> 2;
        kb8[l] = (f & 3) << 3;
    }

    float acc[2][8][4];
#pragma unroll
    for (int a = 0; a < 2; a++)
#pragma unroll
        for (int b = 0; b < 8; b++)
#pragma unroll
            for (int r = 0; r < 4; r++) acc[a][b][r] = 0.f;

    float4 av[4];
    uint4 bhv[2], blv[2];
#pragma unroll
    for (int l = 0; l < 4; l++)
        av[l] = *(const float4*)(x + (size_t)(row0 + ra[l]) * DD + ca4[l]);
#pragma unroll
    for (int l = 0; l < 2; l++) {
        size_t gb = (size_t)(col0 + rb[l]) * DD + kb8[l];
        bhv[l] = *(const uint4*)&g_whi[gb];
        blv[l] = *(const uint4*)&g_wlo[gb];
    }

    for (int kb = 0; kb < DD; kb += GBK) {
#pragma unroll
        for (int l = 0; l < 4; l++) {
            uint32_t h01, h23, l01, l23;
            split4(av[l], h01, h23, l01, l23);
            *(uint2*)&Ah[ra[l] * SA + ca4[l]] = make_uint2(h01, h23);
            *(uint2*)&Al[ra[l] * SA + ca4[l]] = make_uint2(l01, l23);
        }
#pragma unroll
        for (int l = 0; l < 2; l++) {
            *(uint4*)&Bh[rb[l] * SA + kb8[l]] = bhv[l];
            *(uint4*)&Bl[rb[l] * SA + kb8[l]] = blv[l];
        }
        __syncthreads();

        if (kb + GBK < DD) {
#pragma unroll
            for (int l = 0; l < 4; l++)
                av[l] = *(const float4*)(x + (size_t)(row0 + ra[l]) * DD + kb + GBK + ca4[l]);
#pragma unroll
            for (int l = 0; l < 2; l++) {
                size_t gb = (size_t)(col0 + rb[l]) * DD + kb + GBK + kb8[l];
                bhv[l] = *(const uint4*)&g_whi[gb];
                blv[l] = *(const uint4*)&g_wlo[gb];
            }
        }

#pragma unroll
        for (int ks = 0; ks < GBK; ks += 16) {
            uint32_t afh[2][4], afl[2][4];
            const int kk2 = ks + 2 * tg;
#pragma unroll
            for (int ms = 0; ms < 2; ms++) {
                int rr = wm * 32 + ms * 16 + g;
                afh[ms][0] = *(const uint32_t*)&Ah[rr * SA + kk2];
                afh[ms][1] = *(const uint32_t*)&Ah[(rr + 8) * SA + kk2];
                afh[ms][2] = *(const uint32_t*)&Ah[rr * SA + kk2 + 8];
                afh[ms][3] = *(const uint32_t*)&Ah[(rr + 8) * SA + kk2 + 8];
                afl[ms][0] = *(const uint32_t*)&Al[rr * SA + kk2];
                afl[ms][1] = *(const uint32_t*)&Al[(rr + 8) * SA + kk2];
                afl[ms][2] = *(const uint32_t*)&Al[rr * SA + kk2 + 8];
                afl[ms][3] = *(const uint32_t*)&Al[(rr + 8) * SA + kk2 + 8];
            }
#pragma unroll
            for (int ns = 0; ns < 8; ns++) {
                int nr = wn * 64 + ns * 8 + g;
                uint32_t bh0 = *(const uint32_t*)&Bh[nr * SA + kk2];
                uint32_t bh1 = *(const uint32_t*)&Bh[nr * SA + kk2 + 8];
                uint32_t bl0 = *(const uint32_t*)&Bl[nr * SA + kk2];
                uint32_t bl1 = *(const uint32_t*)&Bl[nr * SA + kk2 + 8];
#pragma unroll
                for (int ms = 0; ms < 2; ms++) {
                    MMA16816(acc[ms][ns], afh[ms], bh0, bh1);
                    MMA16816(acc[ms][ns], afh[ms], bl0, bl1);
                    MMA16816(acc[ms][ns], afl[ms], bh0, bh1);
                }
            }
        }
        __syncthreads();
    }

#pragma unroll
    for (int ms = 0; ms < 2; ms++)
#pragma unroll
        for (int ns = 0; ns < 8; ns++) {
            int m = row0 + wm * 32 + ms * 16 + g;
            int n = col0 + wn * 64 + ns * 8 + tg * 2;
            *(float2*)&g_proj[(size_t)m * NC + n] =
                make_float2(acc[ms][ns][0], acc[ms][ns][1]);
            *(float2*)&g_proj[(size_t)(m + 8) * NC + n] =
                make_float2(acc[ms][ns][2], acc[ms][ns][3]);
        }
}

// ---------------------------------------------------------------------------
// In-chunk Gram: for (chunk,b): G[t*16+u] = k_t . k_u (symmetric).
// ---------------------------------------------------------------------------
__global__ __launch_bounds__(256) void gramc_kernel() {
    const int b  = blockIdx.x & 15;
    const int ch = blockIdx.x >> 4;
    const int tid = threadIdx.x;
    __shared__ float Ks[16][68];

    {
        const int s = tid >> 4, j4 = (tid & 15) * 4;
        float4 kv = *(const float4*)(g_proj + ((size_t)(ch * CCH + s) * BB + b) * NC + j4);
        *(float4*)&Ks[s][j4] = kv;
    }
    __syncthreads();

    const int t = tid >> 4, u = tid & 15;
    float acc = 0.f;
#pragma unroll
    for (int j = 0; j < 64; j++) acc = fmaf(Ks[t][j], Ks[u][j], acc);
    g_gramc[((size_t)ch * CCH + b) * 256 + t * 16 + u] = acc;   // note CCH==BB==16
}

// ---------------------------------------------------------------------------
// scanA v3: ph2 = register E-ladder (no triangular re-scan):
//   E[d] = S_partial . k_d; per step: E[d>=s] = al*E[d] + cc*G[s-1][d];
//   r_s = E[s] immediately. ws reconstructed once by suffix pass.
// ph3b/ph3c unchanged (R10 winner).
// ---------------------------------------------------------------------------
__device__ __forceinline__ float fast_tanh(float x) {
    float r;
    asm("tanh.approx.f32 %0, %1;" : "=f"(r) : "f"(x));
    return r;
}

__global__ __launch_bounds__(256) void scanA_kernel(
    const float* __restrict__ S_in,
    const float* __restrict__ dA,
    const float* __restrict__ bA,
    float* __restrict__ out)
{
    const int b  = blockIdx.x >> 2;
    const int qr = blockIdx.x & 3;
    const int i0 = qr * 16;
    const int tid = threadIdx.x;
    const int il = tid >> 4;          // row in block 0..15
    const int i  = i0 + il;           // global row
    const int c  = tid & 15;          // lane in row
    const int j0 = c * 4;

    __shared__ float Kbuf[2][16 * 68];
    __shared__ float Gbuf[2][256];
    __shared__ float Vbuf[2][16][16];   // [buf][s][row]
    __shared__ float Abuf[2][16][16];
    __shared__ float Wsbuf[16][20];     // [row][ws0..15, pi]
    __shared__ float Grebuf[16][20];    // [row][d]
    __shared__ float Sbuf[16][68];      // [row][j]

    const int sk = il, jk = j0;
    const int sv = il, iv = c;

    float S0, S1, S2, S3;
    {
        float4 si = *(const float4*)(S_in + ((size_t)b * NN + i) * NN + j0);
        S0 = si.x; S1 = si.y; S2 = si.z; S3 = si.w;
        *(float4*)(g_Scs + ((size_t)b * NN + i) * NN + j0) = si;   // Scs[0]
        *(float4*)&Sbuf[il][j0] = si;
    }
    float dah = 0.f, bah = 0.f;
    if (tid < 16) {
        dah = 0.5f * dA[i0 + tid];
        bah = 0.5f * bA[i0 + tid];
    }

    // ---- prologue: stage chunk 0 tiles into buf 0 ----
    {
        float4 kpre = *(const float4*)(g_proj + ((size_t)sk * BB + b) * NC + jk);
        float4 gpre = make_float4(0, 0, 0, 0);
        if (tid < 64) gpre = *(const float4*)(g_gramc + (size_t)b * 256 + tid * 4);
        float vpre = g_proj[((size_t)sv * BB + b) * NC + 64 + i0 + iv];
        float apre = g_proj[((size_t)sv * BB + b) * NC + 192 + i0 + iv];
        *(float4*)&Kbuf[0][sk * 68 + jk] = kpre;
        if (tid < 64) *(float4*)&Gbuf[0][tid * 4] = gpre;
        Vbuf[0][sv][iv] = vpre;
        Abuf[0][sv][iv] = apre;
    }
    __syncthreads();

    // ---- prologue Gre: Gre[il][c] = S_init[il] . k_c (chunk 0) ----
    {
        float acc = 0.f;
#pragma unroll
        for (int j4 = 0; j4 < 64; j4 += 4) {
            float4 sv4 = *(const float4*)&Sbuf[il][j4];
            float4 kv4 = *(const float4*)&Kbuf[0][c * 68 + j4];
            acc = fmaf(sv4.x, kv4.x, acc);
            acc = fmaf(sv4.y, kv4.y, acc);
            acc = fmaf(sv4.z, kv4.z, acc);
            acc = fmaf(sv4.w, kv4.w, acc);
        }
        Grebuf[il][c] = acc;
    }

    // ---- prologue LDG chunk 1 -> regs ----
    float4 kpre, gpre;
    float vpre, apre;
    {
        const size_t tb1 = (size_t)CCH * BB + b;
        kpre = *(const float4*)(g_proj + (tb1 + (size_t)sk * BB) * NC + jk);
        gpre = make_float4(0, 0, 0, 0);
        if (tid < 64)
            gpre = *(const float4*)(g_gramc + ((size_t)1 * BB + b) * 256 + tid * 4);
        vpre = g_proj[(tb1 + (size_t)sv * BB) * NC + 64 + i0 + iv];
        apre = g_proj[(tb1 + (size_t)sv * BB) * NC + 192 + i0 + iv];
    }
    __syncthreads();

    for (int ch = 0; ch < NCH; ch++) {
        const int cb = ch & 1, nb = cb ^ 1;

        // ---- stage regs (chunk ch+1) into buffer nb ----
        *(float4*)&Kbuf[nb][sk * 68 + jk] = kpre;
        if (tid < 64) *(float4*)&Gbuf[nb][tid * 4] = gpre;
        Vbuf[nb][sv][iv] = vpre;
        Abuf[nb][sv][iv] = apre;

        // ---- issue LDGs for chunk ch+2 (pad-safe, PAD_T=32) ----
        {
            const size_t tb2 = (size_t)((ch + 2) * CCH) * BB + b;
            kpre = *(const float4*)(g_proj + (tb2 + (size_t)sk * BB) * NC + jk);
            if (tid < 64)
                gpre = *(const float4*)(g_gramc + ((size_t)(ch + 2) * BB + b) * 256 + tid * 4);
            vpre = g_proj[(tb2 + (size_t)sv * BB) * NC + 64 + i0 + iv];
            apre = g_proj[(tb2 + (size_t)sv * BB) * NC + 192 + i0 + iv];
        }

        // ---- ph2: single-warp register E-ladder (lane = row) ----
        if (tid < 16) {
            const int r = tid;
            float E[16];
#pragma unroll
            for (int d4 = 0; d4 < 16; d4 += 4) {
                float4 f = *(const float4*)&Grebuf[r][d4];
                E[d4] = f.x; E[d4 + 1] = f.y; E[d4 + 2] = f.z; E[d4 + 3] = f.w;
            }
            float alv[16], cvv[16];
            float alp, ccp;
            // step 0
            {
                float xg = fmaf(dah, E[0], fmaf(0.5f, Abuf[cb][0][r], bah));
                alp = fmaf(0.5f, fast_tanh(xg), 0.5f);
                float v0 = Vbuf[cb][0][r];
                ccp = fmaf(-alp, v0, v0);
                alv[0] = alp; cvv[0] = ccp;
            }
#pragma unroll
            for (int s = 1; s < 16; s++) {
                // G row (s-1): needed for the E update
                float g[16];
#pragma unroll
                for (int u4 = 0; u4 < 16; u4 += 4) {
                    float4 f = *(const float4*)&Gbuf[cb][(s - 1) * 16 + u4];
                    g[u4] = f.x; g[u4 + 1] = f.y; g[u4 + 2] = f.z; g[u4 + 3] = f.w;
                }
#pragma unroll
                for (int d = 15; d >= s; d--)       // E[s] first? update E[s] early:
                    E[d] = fmaf(alp, E[d], ccp * g[d]);
                float xg = fmaf(dah, E[s], fmaf(0.5f, Abuf[cb][s][r], bah));
                float al = fmaf(0.5f, fast_tanh(xg), 0.5f);
                float vv = Vbuf[cb][s][r];
                float cc = fmaf(-al, vv, vv);
                alv[s] = al; cvv[s] = cc;
                alp = al; ccp = cc;
            }
            // suffix products -> ws, pi
            float ws[16];
            float suf = 1.f;
#pragma unroll
            for (int u = 15; u >= 0; u--) {
                ws[u] = cvv[u] * suf;
                suf *= alv[u];
            }
#pragma unroll
            for (int u4 = 0; u4 < 16; u4 += 4)
                *(float4*)&Wsbuf[r][u4] =
                    make_float4(ws[u4], ws[u4 + 1], ws[u4 + 2], ws[u4 + 3]);
            Wsbuf[r][16] = suf;
            // batched g_ac stores
            float2* acp = g_ac + ((size_t)(ch * CCH) * BB + b) * NN + i0 + r;
#pragma unroll
            for (int s2 = 0; s2 < 16; s2++)
                acp[(size_t)s2 * BB * NN] = make_float2(alv[s2], cvv[s2]);
        }
        __syncthreads();   // Wsbuf + nb staging visible

        // ---- ph3b: S rank-16 update; write Sbuf + Scs/out ----
        {
            float pi2 = Wsbuf[il][16];
            float n0 = pi2 * S0, n1 = pi2 * S1, n2 = pi2 * S2, n3 = pi2 * S3;
#pragma unroll
            for (int s = 0; s < 16; s++) {
                float w = Wsbuf[il][s];
                float4 k4 = *(const float4*)&Kbuf[cb][s * 68 + j0];
                n0 = fmaf(w, k4.x, n0);
                n1 = fmaf(w, k4.y, n1);
                n2 = fmaf(w, k4.z, n2);
                n3 = fmaf(w, k4.w, n3);
            }
            S0 = n0; S1 = n1; S2 = n2; S3 = n3;
            float4 sv4 = make_float4(S0, S1, S2, S3);
            *(float4*)&Sbuf[il][j0] = sv4;
            if (ch < NCH - 1)
                *(float4*)(g_Scs + (size_t)(ch + 1) * BB * NN * NN
                           + ((size_t)b * NN + i) * NN + j0) = sv4;
            else
                *(float4*)(out + (size_t)TT * BB * NN
                           + ((size_t)b * NN + i) * NN + j0) = sv4;
        }
        __syncthreads();   // Sbuf visible

        // ---- ph3c: Gre[il][c] = Sbuf[il] . Knext[c] (no shuffles) ----
        {
            float acc = 0.f;
#pragma unroll
            for (int j4 = 0; j4 < 64; j4 += 4) {
                float4 sv4 = *(const float4*)&Sbuf[il][j4];
                float4 kv4 = *(const float4*)&Kbuf[nb][c * 68 + j4];
                acc = fmaf(sv4.x, kv4.x, acc);
                acc = fmaf(sv4.y, kv4.y, acc);
                acc = fmaf(sv4.z, kv4.z, acc);
                acc = fmaf(sv4.w, kv4.w, acc);
            }
            Grebuf[il][c] = acc;
        }
        __syncthreads();   // Grebuf visible for next ph2
    }
}

// ---------------------------------------------------------------------------
// b3: outputs. Block per (b,chunk), 64 threads (thread = row i).
// ---------------------------------------------------------------------------
__global__ __launch_bounds__(64) void b3_out(float* __restrict__ out) {
    const int b  = blockIdx.x & 15;
    const int ch = blockIdx.x >> 4;
    const int tid = threadIdx.x;          // = i

    __shared__ float Ks[CCH][68];
    __shared__ float Qs[CCH][68];
    __shared__ float Dm[CCH][CCH];

#pragma unroll
    for (int s = 0; s < CCH; s++) {
        const float* P = g_proj + ((size_t)(ch * CCH + s) * BB + b) * NC;
        Ks[s][tid] = P[tid];
        Qs[s][tid] = P[128 + tid];
    }
    __syncthreads();

#pragma unroll
    for (int e = 0; e < 4; e++) {
        int id = tid * 4 + e;
        int s = id >> 4, t = id & 15;
        float a = 0.f;
#pragma unroll
        for (int j = 0; j < NN; j++) a = fmaf(Ks[s][j], Qs[t][j], a);
        Dm[s][t] = a;
    }
    __syncthreads();

    float Sr[NN];
    {
        const float* P = g_Scs + (size_t)ch * BB * NN * NN + ((size_t)b * NN + tid) * NN;
#pragma unroll
        for (int j = 0; j < NN; j += 4) {
            float4 f = *(const float4*)(P + j);
            Sr[j] = f.x; Sr[j + 1] = f.y; Sr[j + 2] = f.z; Sr[j + 3] = f.w;
        }
    }

    float gt[CCH];
#pragma unroll
    for (int t = 0; t < CCH; t++) {
        float a = 0.f;
#pragma unroll
        for (int j = 0; j < NN; j++) a = fmaf(Sr[j], Qs[t][j], a);
        gt[t] = a;
    }

    float al[CCH], cc[CCH];
#pragma unroll
    for (int s = 0; s < CCH; s++) {
        float2 v = g_ac[((size_t)(ch * CCH + s) * BB + b) * NN + tid];
        al[s] = v.x; cc[s] = v.y;
    }

    float w[CCH];
    float pi = 1.f;
#pragma unroll
    for (int t = 0; t < CCH; t++) {
        float a = al[t];
        pi *= a;
#pragma unroll
        for (int s = 0; s < CCH; s++)
            if (s < t) w[s] *= a;
        w[t] = cc[t];
        float o = pi * gt[t];
#pragma unroll
        for (int s = 0; s < CCH; s++)
            if (s <= t) o = fmaf(w[s], Dm[s][t], o);
        float sg = fmaf(0.5f, fast_tanh(0.5f * o), 0.5f);
        out[((size_t)(ch * CCH + t) * BB + b) * NN + tid] = o * o * sg;
    }
}

extern "C" void kernel_launch(void* const* d_in, const int* in_sizes, int n_in,
                              void* d_out, int out_size) {
    const float* x  = (const float*)d_in[0];
    const float* S  = (const float*)d_in[1];
    const float* Wk = (const float*)d_in[2];
    const float* Wv = (const float*)d_in[3];
    const float* Wq = (const float*)d_in[4];
    const float* Wa = (const float*)d_in[5];
    const float* da = (const float*)d_in[6];
    const float* ba = (const float*)d_in[7];
    float* out = (float*)d_out;

    convert_w<<<NC * DD / (256 * 4), 256>>>(Wk, Wv, Wq, Wa);
    dim3 ggrid(NC / GBN, MT / GBM);
    mma_gemm<<<ggrid, 256>>>(x);
    gramc_kernel<<<NCH * BB, 256>>>();
    scanA_kernel<<<BB * 4, 256>>>(S, da, ba, out);
    b3_out<<<NCH * BB, 64>>>(out);
}